// round 1
// baseline (speedup 1.0000x reference)
#include <cuda_runtime.h>
#include <cuda_bf16.h>
#include <math.h>

// Problem constants
#define NB   16          // batch
#define NF   64          // base channels
#define GC   64          // growth / out channels per layer
#define KK   8           // num expert kernels
#define HH   96
#define WW   96
#define HW   (HH*WW)     // 9216
#define CTOT 320         // total concat channels (x, x1..x4)

// ---------------------------------------------------------------------------
// Scratch (static __device__ allocations; no runtime allocs allowed)
// ---------------------------------------------------------------------------
__device__ float g_concat[(size_t)NB * CTOT * HW];      // 188.7 MB: [b][c][h][w]
__device__ float g_pooled[NB * CTOT];                   // GAP sums (means)
__device__ float g_attn[NB * KK];
__device__ float g_bk[NB * GC];
__device__ float g_wk[(size_t)NB * GC * CTOT * 9];      // mixed per-sample weights (max layer)

// ---------------------------------------------------------------------------
// Copy input x into concat channels [0,64)
// ---------------------------------------------------------------------------
__global__ void copyx_kernel(const float* __restrict__ x) {
    int idx = blockIdx.x * 256 + threadIdx.x;
    int total = NB * NF * HW;
    if (idx >= total) return;
    int b = idx / (NF * HW);
    int rem = idx - b * (NF * HW);
    g_concat[(size_t)b * CTOT * HW + rem] = x[idx];
}

// ---------------------------------------------------------------------------
// Global average pool of 64 channels starting at ch_off (reads g_concat)
// grid: (64, NB), block: 256
// ---------------------------------------------------------------------------
__global__ void gap_kernel(int ch_off) {
    int c = blockIdx.x;
    int b = blockIdx.y;
    int t = threadIdx.x;
    const float* p = g_concat + ((size_t)b * CTOT + ch_off + c) * HW;
    float s = 0.f;
    for (int i = t; i < HW; i += 256) s += p[i];
    __shared__ float red[256];
    red[t] = s;
    __syncthreads();
    for (int o = 128; o > 0; o >>= 1) {
        if (t < o) red[t] += red[t + o];
        __syncthreads();
    }
    if (t == 0) g_pooled[b * CTOT + ch_off + c] = red[0] * (1.f / (float)HW);
}

// ---------------------------------------------------------------------------
// Attention MLP per sample: pooled -> fc1(relu) -> fc2 -> softmax -> attn, bk
// grid: NB blocks, block: 128
// ---------------------------------------------------------------------------
template <int CIN>
__global__ void attn_kernel(const float* __restrict__ aw1, const float* __restrict__ ab1,
                            const float* __restrict__ aw2, const float* __restrict__ ab2,
                            const float* __restrict__ bvec) {
    const int HID = CIN / 4;
    int b = blockIdx.x;
    int t = threadIdx.x;
    __shared__ float sp[CIN];
    __shared__ float sh[HID];
    __shared__ float sl[KK];
    __shared__ float sa[KK];

    for (int i = t; i < CIN; i += 128) sp[i] = g_pooled[b * CTOT + i];
    __syncthreads();

    if (t < HID) {
        float s = ab1[t];
        const float* row = aw1 + (size_t)t * CIN;
        for (int c = 0; c < CIN; c++) s += row[c] * sp[c];
        sh[t] = s > 0.f ? s : 0.f;
    }
    __syncthreads();

    if (t < KK) {
        float s = ab2[t];
        const float* row = aw2 + (size_t)t * HID;
        for (int j = 0; j < HID; j++) s += row[j] * sh[j];
        sl[t] = s;
    }
    __syncthreads();

    if (t == 0) {
        float m = sl[0];
        for (int k = 1; k < KK; k++) m = fmaxf(m, sl[k]);
        float den = 0.f;
        for (int k = 0; k < KK; k++) { float e = expf(sl[k] - m); sa[k] = e; den += e; }
        float inv = 1.f / den;
        for (int k = 0; k < KK; k++) { sa[k] *= inv; g_attn[b * KK + k] = sa[k]; }
    }
    __syncthreads();

    if (t < GC) {
        float s = 0.f;
        #pragma unroll
        for (int k = 0; k < KK; k++) s += sa[k] * bvec[k * GC + t];
        g_bk[b * GC + t] = s;
    }
}

// ---------------------------------------------------------------------------
// Mix expert weights with attention: wk[b][o][c][t] = sum_k attn[b][k]*w[k][o][c][t]
// ---------------------------------------------------------------------------
__global__ void mix_kernel(const float* __restrict__ w, int per_b, int total) {
    int i = blockIdx.x * 256 + threadIdx.x;
    if (i >= total) return;
    int b = i / per_b;
    int r = i - b * per_b;
    float s = 0.f;
    #pragma unroll
    for (int k = 0; k < KK; k++)
        s += g_attn[b * KK + k] * w[(size_t)k * per_b + r];
    g_wk[i] = s;
}

// ---------------------------------------------------------------------------
// Direct 3x3 conv, pad 1, per-sample weights from g_wk.
// Block: 256 threads = 8 oc-groups x 32 columns. Tile: 32 wide x 8 tall, all 64 oc.
// Each thread: 8 oc x 8 rows register tile (64 accumulators).
// grid: (3, 12, NB)
// ---------------------------------------------------------------------------
#define CKC 8  // cin chunk

template <int CIN, bool FINAL>
__global__ __launch_bounds__(256, 2)
void conv_kernel(float* __restrict__ dout, int out_ch_off) {
    __shared__ float s_in[CKC][10][34];
    __shared__ float s_w[GC][CKC * 9];

    const int bx = blockIdx.x;     // 0..2
    const int by = blockIdx.y;     // 0..11
    const int b  = blockIdx.z;
    const int t  = threadIdx.x;
    const int x   = t & 31;
    const int ocg = t >> 5;        // 0..7 (== warp id)
    const int gx0 = bx * 32;
    const int gy0 = by * 8;

    const float* inb = g_concat + (size_t)b * CTOT * HW;
    const float* wkb = g_wk + (size_t)b * GC * CIN * 9;

    float acc[8][8];
    #pragma unroll
    for (int j = 0; j < 8; j++)
        #pragma unroll
        for (int y = 0; y < 8; y++) acc[j][y] = 0.f;

    #pragma unroll 1
    for (int c0 = 0; c0 < CIN; c0 += CKC) {
        __syncthreads();
        // load input tile (with halo, zero pad)
        for (int i = t; i < CKC * 340; i += 256) {
            int c = i / 340;
            int rem = i - c * 340;
            int r = rem / 34;
            int col = rem - r * 34;
            int gy = gy0 + r - 1;
            int gx = gx0 + col - 1;
            float v = 0.f;
            if ((unsigned)gy < HH && (unsigned)gx < WW)
                v = inb[(size_t)(c0 + c) * HW + gy * WW + gx];
            s_in[c][r][col] = v;
        }
        // load weight chunk: per oc, CKC*9 consecutive floats
        for (int i = t; i < GC * CKC * 9; i += 256) {
            int oc = i / (CKC * 9);
            int j  = i - oc * (CKC * 9);
            s_w[oc][j] = wkb[(size_t)oc * (CIN * 9) + c0 * 9 + j];
        }
        __syncthreads();

        #pragma unroll 1
        for (int c = 0; c < CKC; c++) {
            #pragma unroll
            for (int dx = 0; dx < 3; dx++) {
                float iv[10];
                #pragma unroll
                for (int r = 0; r < 10; r++) iv[r] = s_in[c][r][x + dx];
                #pragma unroll
                for (int j = 0; j < 8; j++) {
                    const float* wr = &s_w[ocg * 8 + j][c * 9 + dx];
                    float w0 = wr[0], w1 = wr[3], w2 = wr[6];
                    #pragma unroll
                    for (int y = 0; y < 8; y++) {
                        acc[j][y] = fmaf(w0, iv[y],     acc[j][y]);
                        acc[j][y] = fmaf(w1, iv[y + 1], acc[j][y]);
                        acc[j][y] = fmaf(w2, iv[y + 2], acc[j][y]);
                    }
                }
            }
        }
    }

    // epilogue
    const int oc0 = ocg * 8;
    #pragma unroll
    for (int j = 0; j < 8; j++) {
        int oc = oc0 + j;
        float bias = g_bk[b * GC + oc];
        #pragma unroll
        for (int y = 0; y < 8; y++) {
            float v = acc[j][y] + bias;
            size_t pix = (size_t)(gy0 + y) * WW + gx0 + x;
            if (FINAL) {
                float xr = g_concat[((size_t)b * CTOT + oc) * HW + pix];
                dout[((size_t)b * GC + oc) * HW + pix] = 0.2f * v + xr;
            } else {
                v = v >= 0.f ? v : 0.2f * v;
                g_concat[((size_t)b * CTOT + out_ch_off + oc) * HW + pix] = v;
            }
        }
    }
}

// ---------------------------------------------------------------------------
// Host orchestration
// ---------------------------------------------------------------------------
extern "C" void kernel_launch(void* const* d_in, const int* in_sizes, int n_in,
                              void* d_out, int out_size) {
    const float* x = (const float*)d_in[0];
    const float *W[5], *Bv[5], *A1[5], *Ab1[5], *A2[5], *Ab2[5];
    for (int i = 0; i < 5; i++) {
        W[i]   = (const float*)d_in[1 + 6 * i + 0];
        Bv[i]  = (const float*)d_in[1 + 6 * i + 1];
        A1[i]  = (const float*)d_in[1 + 6 * i + 2];
        Ab1[i] = (const float*)d_in[1 + 6 * i + 3];
        A2[i]  = (const float*)d_in[1 + 6 * i + 4];
        Ab2[i] = (const float*)d_in[1 + 6 * i + 5];
    }
    float* out = (float*)d_out;

    dim3 cgrid(3, 12, NB);

    copyx_kernel<<<(NB * NF * HW + 255) / 256, 256>>>(x);
    gap_kernel<<<dim3(64, NB), 256>>>(0);

    // Layer 1 (cin=64)
    {
        const int CIN = 64, per_b = GC * CIN * 9, total = NB * per_b;
        attn_kernel<64><<<NB, 128>>>(A1[0], Ab1[0], A2[0], Ab2[0], Bv[0]);
        mix_kernel<<<(total + 255) / 256, 256>>>(W[0], per_b, total);
        conv_kernel<64, false><<<cgrid, 256>>>(nullptr, 64);
        gap_kernel<<<dim3(64, NB), 256>>>(64);
    }
    // Layer 2 (cin=128)
    {
        const int CIN = 128, per_b = GC * CIN * 9, total = NB * per_b;
        attn_kernel<128><<<NB, 128>>>(A1[1], Ab1[1], A2[1], Ab2[1], Bv[1]);
        mix_kernel<<<(total + 255) / 256, 256>>>(W[1], per_b, total);
        conv_kernel<128, false><<<cgrid, 256>>>(nullptr, 128);
        gap_kernel<<<dim3(64, NB), 256>>>(128);
    }
    // Layer 3 (cin=192)
    {
        const int CIN = 192, per_b = GC * CIN * 9, total = NB * per_b;
        attn_kernel<192><<<NB, 128>>>(A1[2], Ab1[2], A2[2], Ab2[2], Bv[2]);
        mix_kernel<<<(total + 255) / 256, 256>>>(W[2], per_b, total);
        conv_kernel<192, false><<<cgrid, 256>>>(nullptr, 192);
        gap_kernel<<<dim3(64, NB), 256>>>(192);
    }
    // Layer 4 (cin=256)
    {
        const int CIN = 256, per_b = GC * CIN * 9, total = NB * per_b;
        attn_kernel<256><<<NB, 128>>>(A1[3], Ab1[3], A2[3], Ab2[3], Bv[3]);
        mix_kernel<<<(total + 255) / 256, 256>>>(W[3], per_b, total);
        conv_kernel<256, false><<<cgrid, 256>>>(nullptr, 256);
        gap_kernel<<<dim3(64, NB), 256>>>(256);
    }
    // Layer 5 (cin=320) -> final output with residual
    {
        const int CIN = 320, per_b = GC * CIN * 9, total = NB * per_b;
        attn_kernel<320><<<NB, 128>>>(A1[4], Ab1[4], A2[4], Ab2[4], Bv[4]);
        mix_kernel<<<(total + 255) / 256, 256>>>(W[4], per_b, total);
        conv_kernel<320, true><<<cgrid, 256>>>(out, 0);
    }
}

// round 2
// speedup vs baseline: 1.1269x; 1.1269x over previous
#include <cuda_runtime.h>
#include <cuda_bf16.h>
#include <math.h>

// Problem constants
#define NB   16          // batch
#define NF   64          // base channels
#define GC   64          // growth / out channels per layer
#define KK   8           // num expert kernels
#define HH   96
#define WW   96
#define HW   (HH*WW)     // 9216
#define CTOT 320         // total concat channels (x, x1..x4)

// ---------------------------------------------------------------------------
// Scratch (static __device__ allocations; no runtime allocs allowed)
// ---------------------------------------------------------------------------
__device__ float g_concat[(size_t)NB * CTOT * HW];      // [b][c][h][w]
__device__ float g_pooled[NB * CTOT];
__device__ float g_attn[NB * KK];
__device__ float g_bk[NB * GC];
__device__ float g_wk[(size_t)NB * GC * CTOT * 9];      // mixed per-sample weights

// ---------------------------------------------------------------------------
// Copy input x into concat channels [0,64)
// ---------------------------------------------------------------------------
__global__ void copyx_kernel(const float* __restrict__ x) {
    int idx = blockIdx.x * 256 + threadIdx.x;
    int total = NB * NF * HW;
    if (idx >= total) return;
    int b = idx / (NF * HW);
    int rem = idx - b * (NF * HW);
    g_concat[(size_t)b * CTOT * HW + rem] = x[idx];
}

// ---------------------------------------------------------------------------
// Global average pool of 64 channels starting at ch_off
// grid: (64, NB), block: 256
// ---------------------------------------------------------------------------
__global__ void gap_kernel(int ch_off) {
    int c = blockIdx.x;
    int b = blockIdx.y;
    int t = threadIdx.x;
    const float* p = g_concat + ((size_t)b * CTOT + ch_off + c) * HW;
    float s = 0.f;
    for (int i = t; i < HW; i += 256) s += p[i];
    __shared__ float red[256];
    red[t] = s;
    __syncthreads();
    for (int o = 128; o > 0; o >>= 1) {
        if (t < o) red[t] += red[t + o];
        __syncthreads();
    }
    if (t == 0) g_pooled[b * CTOT + ch_off + c] = red[0] * (1.f / (float)HW);
}

// ---------------------------------------------------------------------------
// Attention MLP per sample
// ---------------------------------------------------------------------------
template <int CIN>
__global__ void attn_kernel(const float* __restrict__ aw1, const float* __restrict__ ab1,
                            const float* __restrict__ aw2, const float* __restrict__ ab2,
                            const float* __restrict__ bvec) {
    const int HID = CIN / 4;
    int b = blockIdx.x;
    int t = threadIdx.x;
    __shared__ float sp[CIN];
    __shared__ float sh[HID];
    __shared__ float sl[KK];
    __shared__ float sa[KK];

    for (int i = t; i < CIN; i += 128) sp[i] = g_pooled[b * CTOT + i];
    __syncthreads();

    if (t < HID) {
        float s = ab1[t];
        const float* row = aw1 + (size_t)t * CIN;
        for (int c = 0; c < CIN; c++) s += row[c] * sp[c];
        sh[t] = s > 0.f ? s : 0.f;
    }
    __syncthreads();

    if (t < KK) {
        float s = ab2[t];
        const float* row = aw2 + (size_t)t * HID;
        for (int j = 0; j < HID; j++) s += row[j] * sh[j];
        sl[t] = s;
    }
    __syncthreads();

    if (t == 0) {
        float m = sl[0];
        for (int k = 1; k < KK; k++) m = fmaxf(m, sl[k]);
        float den = 0.f;
        for (int k = 0; k < KK; k++) { float e = expf(sl[k] - m); sa[k] = e; den += e; }
        float inv = 1.f / den;
        for (int k = 0; k < KK; k++) { sa[k] *= inv; g_attn[b * KK + k] = sa[k]; }
    }
    __syncthreads();

    if (t < GC) {
        float s = 0.f;
        #pragma unroll
        for (int k = 0; k < KK; k++) s += sa[k] * bvec[k * GC + t];
        g_bk[b * GC + t] = s;
    }
}

// ---------------------------------------------------------------------------
// Mix expert weights: wk[b][o][c][t] = sum_k attn[b][k]*w[k][o][c][t]
// ---------------------------------------------------------------------------
__global__ void mix_kernel(const float* __restrict__ w, int per_b, int total) {
    int i = blockIdx.x * 256 + threadIdx.x;
    if (i >= total) return;
    int b = i / per_b;
    int r = i - b * per_b;
    float s = 0.f;
    #pragma unroll
    for (int k = 0; k < KK; k++)
        s += g_attn[b * KK + k] * w[(size_t)k * per_b + r];
    g_wk[i] = s;
}

// ---------------------------------------------------------------------------
// Direct 3x3 conv, pad 1, per-sample weights, FFMA2 (fma.rn.f32x2) inner loop.
// Block: 256 threads = 8 oc-groups x 32 columns. Tile: 32w x 8h x 64oc.
// Each thread: 8 oc x 8 rows -> 32 packed f32x2 accumulators (oc-pairs).
// grid: (3, 12, NB)
// ---------------------------------------------------------------------------
#define CKC 8           // cin chunk
#define WPAD 66         // padded row stride (floats) for s_w rows; even -> 8B aligned

template <int CIN, bool FINAL>
__global__ __launch_bounds__(256, 2)
void conv_kernel(float* __restrict__ dout, int out_ch_off) {
    __shared__ float s_in[CKC][10][34];
    __shared__ __align__(16) float s_w[CKC * 9 * WPAD];   // [c*9+tap][oc], oc contiguous

    const int bx = blockIdx.x;
    const int by = blockIdx.y;
    const int b  = blockIdx.z;
    const int t  = threadIdx.x;
    const int x   = t & 31;
    const int ocg = t >> 5;        // warp id -> oc group
    const int gx0 = bx * 32;
    const int gy0 = by * 8;
    const int oc0 = ocg * 8;

    const float* inb = g_concat + (size_t)b * CTOT * HW;
    const float* wkb = g_wk + (size_t)b * GC * CIN * 9;

    // packed accumulators: acc2[jp][y] holds (oc0+2jp, oc0+2jp+1)
    unsigned long long acc2[4][8];
    #pragma unroll
    for (int jp = 0; jp < 4; jp++)
        #pragma unroll
        for (int y = 0; y < 8; y++) acc2[jp][y] = 0ULL;

    #pragma unroll 1
    for (int c0 = 0; c0 < CIN; c0 += CKC) {
        __syncthreads();
        // load input tile (with halo, zero pad)
        for (int i = t; i < CKC * 340; i += 256) {
            int c = i / 340;
            int rem = i - c * 340;
            int r = rem / 34;
            int col = rem - r * 34;
            int gy = gy0 + r - 1;
            int gx = gx0 + col - 1;
            float v = 0.f;
            if ((unsigned)gy < HH && (unsigned)gx < WW)
                v = inb[(size_t)(c0 + c) * HW + gy * WW + gx];
            s_in[c][r][col] = v;
        }
        // load weight chunk transposed: s_w[(c*9+tap)*WPAD + oc] = wk[oc][(c0+c)*9+tap]
        for (int i = t; i < GC * CKC * 9; i += 256) {
            int oc = i / (CKC * 9);
            int j  = i - oc * (CKC * 9);      // j = c*9 + tap
            s_w[j * WPAD + oc] = wkb[(size_t)oc * (CIN * 9) + c0 * 9 + j];
        }
        __syncthreads();

        #pragma unroll 1
        for (int c = 0; c < CKC; c++) {
            const int rowb = c * 9;
            #pragma unroll
            for (int dx = 0; dx < 3; dx++) {
                // load column of input values, duplicate into both f32x2 lanes
                unsigned long long ivp[10];
                #pragma unroll
                for (int r = 0; r < 10; r++) {
                    float v = s_in[c][r][x + dx];
                    asm("mov.b64 %0, {%1, %1};" : "=l"(ivp[r]) : "f"(v));
                }
                #pragma unroll
                for (int jp = 0; jp < 4; jp++) {
                    const float* wb = s_w + (rowb + dx) * WPAD + oc0 + 2 * jp;
                    unsigned long long w0 = *(const unsigned long long*)(wb);
                    unsigned long long w1 = *(const unsigned long long*)(wb + 3 * WPAD);
                    unsigned long long w2 = *(const unsigned long long*)(wb + 6 * WPAD);
                    #pragma unroll
                    for (int y = 0; y < 8; y++) {
                        asm("fma.rn.f32x2 %0, %1, %2, %0;" : "+l"(acc2[jp][y]) : "l"(w0), "l"(ivp[y]));
                        asm("fma.rn.f32x2 %0, %1, %2, %0;" : "+l"(acc2[jp][y]) : "l"(w1), "l"(ivp[y + 1]));
                        asm("fma.rn.f32x2 %0, %1, %2, %0;" : "+l"(acc2[jp][y]) : "l"(w2), "l"(ivp[y + 2]));
                    }
                }
            }
        }
    }

    // epilogue
    #pragma unroll
    for (int jp = 0; jp < 4; jp++) {
        int ocA = oc0 + 2 * jp;
        int ocB = ocA + 1;
        float biasA = g_bk[b * GC + ocA];
        float biasB = g_bk[b * GC + ocB];
        #pragma unroll
        for (int y = 0; y < 8; y++) {
            float lo, hi;
            asm("mov.b64 {%0, %1}, %2;" : "=f"(lo), "=f"(hi) : "l"(acc2[jp][y]));
            float vA = lo + biasA;
            float vB = hi + biasB;
            size_t pix = (size_t)(gy0 + y) * WW + gx0 + x;
            if (FINAL) {
                float xrA = g_concat[((size_t)b * CTOT + ocA) * HW + pix];
                float xrB = g_concat[((size_t)b * CTOT + ocB) * HW + pix];
                dout[((size_t)b * GC + ocA) * HW + pix] = 0.2f * vA + xrA;
                dout[((size_t)b * GC + ocB) * HW + pix] = 0.2f * vB + xrB;
            } else {
                vA = vA >= 0.f ? vA : 0.2f * vA;
                vB = vB >= 0.f ? vB : 0.2f * vB;
                g_concat[((size_t)b * CTOT + out_ch_off + ocA) * HW + pix] = vA;
                g_concat[((size_t)b * CTOT + out_ch_off + ocB) * HW + pix] = vB;
            }
        }
    }
}

// ---------------------------------------------------------------------------
// Host orchestration
// ---------------------------------------------------------------------------
extern "C" void kernel_launch(void* const* d_in, const int* in_sizes, int n_in,
                              void* d_out, int out_size) {
    const float* x = (const float*)d_in[0];
    const float *W[5], *Bv[5], *A1[5], *Ab1[5], *A2[5], *Ab2[5];
    for (int i = 0; i < 5; i++) {
        W[i]   = (const float*)d_in[1 + 6 * i + 0];
        Bv[i]  = (const float*)d_in[1 + 6 * i + 1];
        A1[i]  = (const float*)d_in[1 + 6 * i + 2];
        Ab1[i] = (const float*)d_in[1 + 6 * i + 3];
        A2[i]  = (const float*)d_in[1 + 6 * i + 4];
        Ab2[i] = (const float*)d_in[1 + 6 * i + 5];
    }
    float* out = (float*)d_out;

    dim3 cgrid(3, 12, NB);

    copyx_kernel<<<(NB * NF * HW + 255) / 256, 256>>>(x);
    gap_kernel<<<dim3(64, NB), 256>>>(0);

    // Layer 1 (cin=64)
    {
        const int CIN = 64, per_b = GC * CIN * 9, total = NB * per_b;
        attn_kernel<64><<<NB, 128>>>(A1[0], Ab1[0], A2[0], Ab2[0], Bv[0]);
        mix_kernel<<<(total + 255) / 256, 256>>>(W[0], per_b, total);
        conv_kernel<64, false><<<cgrid, 256>>>(nullptr, 64);
        gap_kernel<<<dim3(64, NB), 256>>>(64);
    }
    // Layer 2 (cin=128)
    {
        const int CIN = 128, per_b = GC * CIN * 9, total = NB * per_b;
        attn_kernel<128><<<NB, 128>>>(A1[1], Ab1[1], A2[1], Ab2[1], Bv[1]);
        mix_kernel<<<(total + 255) / 256, 256>>>(W[1], per_b, total);
        conv_kernel<128, false><<<cgrid, 256>>>(nullptr, 128);
        gap_kernel<<<dim3(64, NB), 256>>>(128);
    }
    // Layer 3 (cin=192)
    {
        const int CIN = 192, per_b = GC * CIN * 9, total = NB * per_b;
        attn_kernel<192><<<NB, 128>>>(A1[2], Ab1[2], A2[2], Ab2[2], Bv[2]);
        mix_kernel<<<(total + 255) / 256, 256>>>(W[2], per_b, total);
        conv_kernel<192, false><<<cgrid, 256>>>(nullptr, 192);
        gap_kernel<<<dim3(64, NB), 256>>>(192);
    }
    // Layer 4 (cin=256)
    {
        const int CIN = 256, per_b = GC * CIN * 9, total = NB * per_b;
        attn_kernel<256><<<NB, 128>>>(A1[3], Ab1[3], A2[3], Ab2[3], Bv[3]);
        mix_kernel<<<(total + 255) / 256, 256>>>(W[3], per_b, total);
        conv_kernel<256, false><<<cgrid, 256>>>(nullptr, 256);
        gap_kernel<<<dim3(64, NB), 256>>>(256);
    }
    // Layer 5 (cin=320) -> final output with residual
    {
        const int CIN = 320, per_b = GC * CIN * 9, total = NB * per_b;
        attn_kernel<320><<<NB, 128>>>(A1[4], Ab1[4], A2[4], Ab2[4], Bv[4]);
        mix_kernel<<<(total + 255) / 256, 256>>>(W[4], per_b, total);
        conv_kernel<320, true><<<cgrid, 256>>>(out, 0);
    }
}

// round 4
// speedup vs baseline: 1.7540x; 1.5564x over previous
#include <cuda_runtime.h>
#include <cuda_bf16.h>
#include <cstdint>
#include <math.h>

#define NB   16
#define NF   64
#define GC   64
#define KK   8
#define HH   96
#define WW   96
#define HW   (HH*WW)
#define CTOT 320

// ---------------------------------------------------------------------------
// Scratch
// ---------------------------------------------------------------------------
__device__ float g_concat[(size_t)NB * HW * CTOT];       // NHWC: [b][pix][c]
__device__ float g_pooled[NB * CTOT];
__device__ float g_attn[NB * KK];
__device__ float g_bk[NB * GC];
__device__ float g_wk2[(size_t)NB * 9 * GC * CTOT];      // [b][tap][oc][c]

// ---------------------------------------------------------------------------
// NCHW -> NHWC transpose of input x into g_concat channels [0,64)
// ---------------------------------------------------------------------------
__global__ void copyx_t(const float* __restrict__ x) {
    __shared__ float sm[64][65];
    int b = blockIdx.y;
    int p0 = blockIdx.x * 64;
    int t = threadIdx.x;
    #pragma unroll
    for (int i = 0; i < 16; i++) {
        int idx = t + i * 256;
        int c = idx >> 6, pl = idx & 63;
        sm[c][pl] = x[((size_t)b * 64 + c) * HW + p0 + pl];
    }
    __syncthreads();
    #pragma unroll
    for (int i = 0; i < 16; i++) {
        int idx = t + i * 256;
        int pl = idx >> 6, c = idx & 63;
        g_concat[((size_t)b * HW + p0 + pl) * CTOT + c] = sm[c][pl];
    }
}

// ---------------------------------------------------------------------------
// GAP over 64 NHWC channels at ch_off. grid(NB), block 256.
// ---------------------------------------------------------------------------
__global__ void gap_nhwc(int ch_off) {
    int b = blockIdx.x;
    int t = threadIdx.x;
    int c = t & 63, pg = t >> 6;
    const float* base = g_concat + (size_t)b * HW * CTOT + ch_off + c;
    float s = 0.f;
    for (int p = pg; p < HW; p += 4)
        s += base[(size_t)p * CTOT];
    __shared__ float red[4][64];
    red[pg][c] = s;
    __syncthreads();
    if (t < 64)
        g_pooled[b * CTOT + ch_off + t] =
            (red[0][t] + red[1][t] + red[2][t] + red[3][t]) * (1.f / (float)HW);
}

// ---------------------------------------------------------------------------
// Attention MLP per sample
// ---------------------------------------------------------------------------
template <int CIN>
__global__ void attn_kernel(const float* __restrict__ aw1, const float* __restrict__ ab1,
                            const float* __restrict__ aw2, const float* __restrict__ ab2,
                            const float* __restrict__ bvec) {
    const int HID = CIN / 4;
    int b = blockIdx.x;
    int t = threadIdx.x;
    __shared__ float sp[CIN];
    __shared__ float sh[HID];
    __shared__ float sl[KK];
    __shared__ float sa[KK];

    for (int i = t; i < CIN; i += 128) sp[i] = g_pooled[b * CTOT + i];
    __syncthreads();
    if (t < HID) {
        float s = ab1[t];
        const float* row = aw1 + (size_t)t * CIN;
        for (int c = 0; c < CIN; c++) s += row[c] * sp[c];
        sh[t] = s > 0.f ? s : 0.f;
    }
    __syncthreads();
    if (t < KK) {
        float s = ab2[t];
        const float* row = aw2 + (size_t)t * HID;
        for (int j = 0; j < HID; j++) s += row[j] * sh[j];
        sl[t] = s;
    }
    __syncthreads();
    if (t == 0) {
        float m = sl[0];
        for (int k = 1; k < KK; k++) m = fmaxf(m, sl[k]);
        float den = 0.f;
        for (int k = 0; k < KK; k++) { float e = expf(sl[k] - m); sa[k] = e; den += e; }
        float inv = 1.f / den;
        for (int k = 0; k < KK; k++) { sa[k] *= inv; g_attn[b * KK + k] = sa[k]; }
    }
    __syncthreads();
    if (t < GC) {
        float s = 0.f;
        #pragma unroll
        for (int k = 0; k < KK; k++) s += sa[k] * bvec[k * GC + t];
        g_bk[b * GC + t] = s;
    }
}

// ---------------------------------------------------------------------------
// Mix expert weights into tap-major layout: g_wk2[b][tap][oc][c]
// ---------------------------------------------------------------------------
template <int CIN>
__global__ void mix2_kernel(const float* __restrict__ w) {
    const int per_b = 9 * GC * CIN;
    int i = blockIdx.x * 256 + threadIdx.x;
    if (i >= NB * per_b) return;
    int b = i / per_b;
    int r = i - b * per_b;
    int tap = r % 9;
    int cc  = (r / 9) % CIN;
    int oc  = r / (9 * CIN);
    float s = 0.f;
    #pragma unroll
    for (int k = 0; k < KK; k++)
        s += g_attn[b * KK + k] * w[(((size_t)k * GC + oc) * CIN + cc) * 9 + tap];
    g_wk2[(((size_t)b * 9 + tap) * GC + oc) * CIN + cc] = s;
}

// ---------------------------------------------------------------------------
// tf32 mma.sync implicit-GEMM conv.
// CTA: 128 pixels (4 rows x 32 cols) x 64 oc. 8 warps = 4(m) x 2(n), each 32x32.
// A halo tile (6x34 pixels x 32ch) loaded ONCE per channel chunk; 9 taps read
// it at shifted addresses. B (64oc x 32ch) double-buffered per tap.
// grid (3, 24, NB), block 256.
// ---------------------------------------------------------------------------
__device__ __forceinline__ void mma_16n8k8(float* c, const uint32_t* a, const uint32_t* b) {
    asm volatile(
        "mma.sync.aligned.m16n8k8.row.col.f32.tf32.tf32.f32 "
        "{%0,%1,%2,%3}, {%4,%5,%6,%7}, {%8,%9}, {%0,%1,%2,%3};"
        : "+f"(c[0]), "+f"(c[1]), "+f"(c[2]), "+f"(c[3])
        : "r"(a[0]), "r"(a[1]), "r"(a[2]), "r"(a[3]), "r"(b[0]), "r"(b[1]));
}

__device__ __forceinline__ uint32_t f2tf32(float v) {
    uint32_t u;
    asm("cvt.rna.tf32.f32 %0, %1;" : "=r"(u) : "f"(v));
    return u;
}

template <int CIN, bool FINAL>
__global__ __launch_bounds__(256, 2)
void conv_mma(float* __restrict__ dout, int out_ch_off) {
    __shared__ uint32_t s_a[204 * 36];        // 6x34 halo pixels x 32ch (pad 36)
    __shared__ uint32_t s_b[2][64 * 36];      // double-buffered 64oc x 32ch
    __shared__ float s_bias[64];

    const int t = threadIdx.x;
    const int lane = t & 31;
    const int wid = t >> 5;
    const int warp_m = wid & 3;               // pixel row within tile
    const int warp_n = wid >> 2;              // oc half
    const int gx0 = blockIdx.x * 32;
    const int gy0 = blockIdx.y * 4;
    const int b = blockIdx.z;

    const float* inb = g_concat + (size_t)b * HW * CTOT;
    const float* wkb = g_wk2 + (size_t)b * (9 * GC * CIN);

    if (t < 64) s_bias[t] = g_bk[b * GC + t];

    float acc[2][4][4];
    #pragma unroll
    for (int mt = 0; mt < 2; mt++)
        #pragma unroll
        for (int nt = 0; nt < 4; nt++)
            #pragma unroll
            for (int q = 0; q < 4; q++) acc[mt][nt][q] = 0.f;

    #pragma unroll 1
    for (int ic = 0; ic < CIN / 32; ic++) {
        const int c0 = ic * 32;
        __syncthreads();
        // A halo tile: 204 pixels x 32 ch (1632 float4 loads)
        #pragma unroll 1
        for (int i = t; i < 1632; i += 256) {
            int pix = i >> 3, q = i & 7;
            int r = pix / 34, cc = pix - r * 34;
            int gy = gy0 + r - 1, gx = gx0 + cc - 1;
            float4 v = make_float4(0.f, 0.f, 0.f, 0.f);
            if ((unsigned)gy < HH && (unsigned)gx < WW)
                v = *(const float4*)(inb + (size_t)(gy * WW + gx) * CTOT + c0 + q * 4);
            uint4 u;
            u.x = f2tf32(v.x); u.y = f2tf32(v.y); u.z = f2tf32(v.z); u.w = f2tf32(v.w);
            *(uint4*)&s_a[pix * 36 + q * 4] = u;
        }
        #pragma unroll 1
        for (int tap = 0; tap < 9; tap++) {
            const int buf = tap & 1;
            // B tile for this tap
            #pragma unroll
            for (int jj = 0; jj < 2; jj++) {
                int j = t + jj * 256;
                int oc = j >> 3, q = j & 7;
                float4 v = *(const float4*)(wkb + ((size_t)tap * GC + oc) * CIN + c0 + q * 4);
                uint4 u;
                u.x = f2tf32(v.x); u.y = f2tf32(v.y); u.z = f2tf32(v.z); u.w = f2tf32(v.w);
                *(uint4*)&s_b[buf][oc * 36 + q * 4] = u;
            }
            __syncthreads();

            const int dy = tap / 3 - 1, dx = tap % 3 - 1;
            const int arow = (warp_m + dy + 1) * 34 + dx + 1;   // halo base for this warp row
            #pragma unroll
            for (int ks = 0; ks < 4; ks++) {
                const int k0 = ks * 8 + (lane & 3);
                uint32_t bf[4][2];
                #pragma unroll
                for (int nt = 0; nt < 4; nt++) {
                    int n = warp_n * 32 + nt * 8 + (lane >> 2);
                    bf[nt][0] = s_b[buf][n * 36 + k0];
                    bf[nt][1] = s_b[buf][n * 36 + k0 + 4];
                }
                uint32_t af[2][4];
                #pragma unroll
                for (int mt = 0; mt < 2; mt++) {
                    int hp0 = arow + mt * 16 + (lane >> 2);
                    af[mt][0] = s_a[hp0 * 36 + k0];
                    af[mt][1] = s_a[(hp0 + 8) * 36 + k0];
                    af[mt][2] = s_a[hp0 * 36 + k0 + 4];
                    af[mt][3] = s_a[(hp0 + 8) * 36 + k0 + 4];
                }
                #pragma unroll
                for (int mt = 0; mt < 2; mt++)
                    #pragma unroll
                    for (int nt = 0; nt < 4; nt++)
                        mma_16n8k8(acc[mt][nt], af[mt], bf[nt]);
            }
        }
    }

    // epilogue: thread owns rows gy0+warp_m, cols per fragment layout
    const int gy = gy0 + warp_m;
    #pragma unroll
    for (int mt = 0; mt < 2; mt++) {
        #pragma unroll
        for (int hi = 0; hi < 2; hi++) {
            int px = mt * 16 + (lane >> 2) + hi * 8;
            size_t pixidx = (size_t)gy * WW + gx0 + px;
            #pragma unroll
            for (int nt = 0; nt < 4; nt++) {
                int oc = warp_n * 32 + nt * 8 + 2 * (lane & 3);
                float v0 = acc[mt][nt][hi * 2 + 0] + s_bias[oc];
                float v1 = acc[mt][nt][hi * 2 + 1] + s_bias[oc + 1];
                if (FINAL) {
                    dout[((size_t)b * GC + oc) * HW + pixidx]     = 0.2f * v0 + inb[pixidx * CTOT + oc];
                    dout[((size_t)b * GC + oc + 1) * HW + pixidx] = 0.2f * v1 + inb[pixidx * CTOT + oc + 1];
                } else {
                    v0 = v0 >= 0.f ? v0 : 0.2f * v0;
                    v1 = v1 >= 0.f ? v1 : 0.2f * v1;
                    *(float2*)&g_concat[((size_t)b * HW + pixidx) * CTOT + out_ch_off + oc] =
                        make_float2(v0, v1);
                }
            }
        }
    }
}

// ---------------------------------------------------------------------------
// Host orchestration
// ---------------------------------------------------------------------------
extern "C" void kernel_launch(void* const* d_in, const int* in_sizes, int n_in,
                              void* d_out, int out_size) {
    const float* x = (const float*)d_in[0];
    const float *W[5], *Bv[5], *A1[5], *Ab1[5], *A2[5], *Ab2[5];
    for (int i = 0; i < 5; i++) {
        W[i]   = (const float*)d_in[1 + 6 * i + 0];
        Bv[i]  = (const float*)d_in[1 + 6 * i + 1];
        A1[i]  = (const float*)d_in[1 + 6 * i + 2];
        Ab1[i] = (const float*)d_in[1 + 6 * i + 3];
        A2[i]  = (const float*)d_in[1 + 6 * i + 4];
        Ab2[i] = (const float*)d_in[1 + 6 * i + 5];
    }
    float* out = (float*)d_out;

    dim3 cgrid(3, 24, NB);

    copyx_t<<<dim3(144, NB), 256>>>(x);
    gap_nhwc<<<NB, 256>>>(0);

    // Layer 1 (cin=64)
    attn_kernel<64><<<NB, 128>>>(A1[0], Ab1[0], A2[0], Ab2[0], Bv[0]);
    mix2_kernel<64><<<(NB * 9 * GC * 64 + 255) / 256, 256>>>(W[0]);
    conv_mma<64, false><<<cgrid, 256>>>(nullptr, 64);
    gap_nhwc<<<NB, 256>>>(64);

    // Layer 2 (cin=128)
    attn_kernel<128><<<NB, 128>>>(A1[1], Ab1[1], A2[1], Ab2[1], Bv[1]);
    mix2_kernel<128><<<(NB * 9 * GC * 128 + 255) / 256, 256>>>(W[1]);
    conv_mma<128, false><<<cgrid, 256>>>(nullptr, 128);
    gap_nhwc<<<NB, 256>>>(128);

    // Layer 3 (cin=192)
    attn_kernel<192><<<NB, 128>>>(A1[2], Ab1[2], A2[2], Ab2[2], Bv[2]);
    mix2_kernel<192><<<(NB * 9 * GC * 192 + 255) / 256, 256>>>(W[2]);
    conv_mma<192, false><<<cgrid, 256>>>(nullptr, 192);
    gap_nhwc<<<NB, 256>>>(192);

    // Layer 4 (cin=256)
    attn_kernel<256><<<NB, 128>>>(A1[3], Ab1[3], A2[3], Ab2[3], Bv[3]);
    mix2_kernel<256><<<(NB * 9 * GC * 256 + 255) / 256, 256>>>(W[3]);
    conv_mma<256, false><<<cgrid, 256>>>(nullptr, 256);
    gap_nhwc<<<NB, 256>>>(256);

    // Layer 5 (cin=320) -> final output with residual
    attn_kernel<320><<<NB, 128>>>(A1[4], Ab1[4], A2[4], Ab2[4], Bv[4]);
    mix2_kernel<320><<<(NB * 9 * GC * 320 + 255) / 256, 256>>>(W[4]);
    conv_mma<320, true><<<cgrid, 256>>>(out, 0);
}

// round 5
// speedup vs baseline: 3.3367x; 1.9023x over previous
#include <cuda_runtime.h>
#include <cuda_bf16.h>
#include <cstdint>
#include <math.h>

#define NB   16
#define NF   64
#define GC   64
#define KK   8
#define HH   96
#define WW   96
#define HW   (HH*WW)
#define CTOT 320

// ---------------------------------------------------------------------------
// Scratch
// ---------------------------------------------------------------------------
__device__ float g_concat[(size_t)NB * HW * CTOT];       // NHWC: [b][pix][c]
__device__ float g_pooled[NB * CTOT];                    // per-channel means
__device__ float g_attn[NB * KK];
__device__ float g_bk[NB * GC];
__device__ float g_wk2[(size_t)NB * 9 * GC * CTOT];      // [b][tap][oc][c]
__device__ float g_partial[(size_t)NB * 144 * 64];       // GAP partials per tile

// ---------------------------------------------------------------------------
// NCHW -> NHWC transpose of input x into g_concat channels [0,64), fused GAP
// partials. grid (144, 16), block 256.
// ---------------------------------------------------------------------------
__global__ void copyx_t(const float* __restrict__ x) {
    __shared__ float sm[64][65];
    __shared__ float red[4][64];
    int b = blockIdx.y;
    int p0 = blockIdx.x * 64;
    int t = threadIdx.x;
    #pragma unroll
    for (int i = 0; i < 16; i++) {
        int idx = t + i * 256;
        int c = idx >> 6, pl = idx & 63;
        sm[c][pl] = x[((size_t)b * 64 + c) * HW + p0 + pl];
    }
    __syncthreads();
    const int c = t & 63;
    float s = 0.f;
    #pragma unroll
    for (int i = 0; i < 16; i++) {
        int pl = (t >> 6) + 4 * i;
        float v = sm[c][pl];
        g_concat[((size_t)b * HW + p0 + pl) * CTOT + c] = v;
        s += v;
    }
    red[t >> 6][c] = s;
    __syncthreads();
    if (t < 64)
        g_partial[((size_t)b * 144 + blockIdx.x) * 64 + t] =
            red[0][t] + red[1][t] + red[2][t] + red[3][t];
}

// ---------------------------------------------------------------------------
// Reduce GAP partials -> g_pooled means. grid(NB), block 256.
// ---------------------------------------------------------------------------
__global__ void reduce_gap(int ntiles, int ch_off) {
    int b = blockIdx.x;
    int t = threadIdx.x;
    int ch = t & 63, grp = t >> 6;
    float s = 0.f;
    for (int tile = grp; tile < ntiles; tile += 4)
        s += g_partial[((size_t)b * 144 + tile) * 64 + ch];
    __shared__ float red[4][64];
    red[grp][ch] = s;
    __syncthreads();
    if (t < 64)
        g_pooled[b * CTOT + ch_off + t] =
            (red[0][t] + red[1][t] + red[2][t] + red[3][t]) * (1.f / (float)HW);
}

// ---------------------------------------------------------------------------
// Attention MLP per sample
// ---------------------------------------------------------------------------
template <int CIN>
__global__ void attn_kernel(const float* __restrict__ aw1, const float* __restrict__ ab1,
                            const float* __restrict__ aw2, const float* __restrict__ ab2,
                            const float* __restrict__ bvec) {
    const int HID = CIN / 4;
    int b = blockIdx.x;
    int t = threadIdx.x;
    __shared__ float sp[CIN];
    __shared__ float sh[HID];
    __shared__ float sl[KK];
    __shared__ float sa[KK];

    for (int i = t; i < CIN; i += 128) sp[i] = g_pooled[b * CTOT + i];
    __syncthreads();
    if (t < HID) {
        float s = ab1[t];
        const float* row = aw1 + (size_t)t * CIN;
        for (int c = 0; c < CIN; c++) s += row[c] * sp[c];
        sh[t] = s > 0.f ? s : 0.f;
    }
    __syncthreads();
    if (t < KK) {
        float s = ab2[t];
        const float* row = aw2 + (size_t)t * HID;
        for (int j = 0; j < HID; j++) s += row[j] * sh[j];
        sl[t] = s;
    }
    __syncthreads();
    if (t == 0) {
        float m = sl[0];
        for (int k = 1; k < KK; k++) m = fmaxf(m, sl[k]);
        float den = 0.f;
        for (int k = 0; k < KK; k++) { float e = expf(sl[k] - m); sa[k] = e; den += e; }
        float inv = 1.f / den;
        for (int k = 0; k < KK; k++) { sa[k] *= inv; g_attn[b * KK + k] = sa[k]; }
    }
    __syncthreads();
    if (t < GC) {
        float s = 0.f;
        #pragma unroll
        for (int k = 0; k < KK; k++) s += sa[k] * bvec[k * GC + t];
        g_bk[b * GC + t] = s;
    }
}

// ---------------------------------------------------------------------------
// Mix expert weights into tap-major layout: g_wk2[b][tap][oc][c]
// ---------------------------------------------------------------------------
template <int CIN>
__global__ void mix2_kernel(const float* __restrict__ w) {
    const int per_b = 9 * GC * CIN;
    int i = blockIdx.x * 256 + threadIdx.x;
    if (i >= NB * per_b) return;
    int b = i / per_b;
    int r = i - b * per_b;
    int tap = r % 9;
    int cc  = (r / 9) % CIN;
    int oc  = r / (9 * CIN);
    float s = 0.f;
    #pragma unroll
    for (int k = 0; k < KK; k++)
        s += g_attn[b * KK + k] * w[(((size_t)k * GC + oc) * CIN + cc) * 9 + tap];
    g_wk2[(((size_t)b * 9 + tap) * GC + oc) * CIN + cc] = s;
}

// ---------------------------------------------------------------------------
// tf32 mma.sync implicit-GEMM conv with register prefetch + fused GAP partials.
// CTA: 128 pixels (4 rows x 32 cols) x 64 oc. 8 warps = 4(m) x 2(n), each 32x32.
// grid (3, 24, NB), block 256.
// ---------------------------------------------------------------------------
__device__ __forceinline__ void mma_16n8k8(float* c, const uint32_t* a, const uint32_t* b) {
    asm volatile(
        "mma.sync.aligned.m16n8k8.row.col.f32.tf32.tf32.f32 "
        "{%0,%1,%2,%3}, {%4,%5,%6,%7}, {%8,%9}, {%0,%1,%2,%3};"
        : "+f"(c[0]), "+f"(c[1]), "+f"(c[2]), "+f"(c[3])
        : "r"(a[0]), "r"(a[1]), "r"(a[2]), "r"(a[3]), "r"(b[0]), "r"(b[1]));
}

__device__ __forceinline__ uint32_t f2tf32(float v) {
    uint32_t u;
    asm("cvt.rna.tf32.f32 %0, %1;" : "=r"(u) : "f"(v));
    return u;
}

template <int CIN, bool FINAL>
__global__ __launch_bounds__(256, 2)
void conv_mma(float* __restrict__ dout, int out_ch_off) {
    __shared__ uint32_t s_a[204 * 36];        // 6x34 halo pixels x 32ch (pad 36)
    __shared__ uint32_t s_b[2][64 * 36];      // double-buffered 64oc x 32ch
    __shared__ float s_bias[64];
    __shared__ float s_red[4][64];

    const int t = threadIdx.x;
    const int lane = t & 31;
    const int wid = t >> 5;
    const int warp_m = wid & 3;
    const int warp_n = wid >> 2;
    const int gx0 = blockIdx.x * 32;
    const int gy0 = blockIdx.y * 4;
    const int b = blockIdx.z;
    const int NC = CIN / 32;

    const float* inb = g_concat + (size_t)b * HW * CTOT;
    const float* wkb = g_wk2 + (size_t)b * (9 * GC * CIN);

    if (t < 64) s_bias[t] = g_bk[b * GC + t];

    float acc[2][4][4];
    #pragma unroll
    for (int mt = 0; mt < 2; mt++)
        #pragma unroll
        for (int nt = 0; nt < 4; nt++)
            #pragma unroll
            for (int q = 0; q < 4; q++) acc[mt][nt][q] = 0.f;

    float4 pfA[7];
    float4 pfB0, pfB1;

    // ---- prefetch helpers ----
    auto loadA = [&](int c0) {
        #pragma unroll
        for (int k = 0; k < 7; k++) {
            int i = t + k * 256;
            float4 v = make_float4(0.f, 0.f, 0.f, 0.f);
            if (i < 1632) {
                int pix = i >> 3, q = i & 7;
                int r = pix / 34, cc = pix - r * 34;
                int gy = gy0 + r - 1, gx = gx0 + cc - 1;
                if ((unsigned)gy < HH && (unsigned)gx < WW)
                    v = *(const float4*)(inb + (size_t)(gy * WW + gx) * CTOT + c0 + q * 4);
            }
            pfA[k] = v;
        }
    };
    auto storeA = [&]() {
        #pragma unroll
        for (int k = 0; k < 7; k++) {
            int i = t + k * 256;
            if (i < 1632) {
                int pix = i >> 3, q = i & 7;
                uint4 u;
                u.x = f2tf32(pfA[k].x); u.y = f2tf32(pfA[k].y);
                u.z = f2tf32(pfA[k].z); u.w = f2tf32(pfA[k].w);
                *(uint4*)&s_a[pix * 36 + q * 4] = u;
            }
        }
    };
    auto loadB = [&](int tap, int c0) {
        int oc0 = t >> 3, q0 = t & 7;
        pfB0 = *(const float4*)(wkb + ((size_t)tap * GC + oc0) * CIN + c0 + q0 * 4);
        int j1 = t + 256;
        int oc1 = j1 >> 3, q1 = j1 & 7;
        pfB1 = *(const float4*)(wkb + ((size_t)tap * GC + oc1) * CIN + c0 + q1 * 4);
    };
    auto storeB = [&](int buf) {
        uint4 u;
        u.x = f2tf32(pfB0.x); u.y = f2tf32(pfB0.y); u.z = f2tf32(pfB0.z); u.w = f2tf32(pfB0.w);
        *(uint4*)&s_b[buf][(t >> 3) * 36 + (t & 7) * 4] = u;
        int j1 = t + 256;
        u.x = f2tf32(pfB1.x); u.y = f2tf32(pfB1.y); u.z = f2tf32(pfB1.z); u.w = f2tf32(pfB1.w);
        *(uint4*)&s_b[buf][(j1 >> 3) * 36 + (j1 & 7) * 4] = u;
    };

    loadA(0);
    loadB(0, 0);

    #pragma unroll 1
    for (int ic = 0; ic < NC; ic++) {
        const int c0 = ic * 32;
        __syncthreads();          // prior chunk's s_a readers done
        storeA();
        #pragma unroll 1
        for (int tap = 0; tap < 9; tap++) {
            const int buf = tap & 1;
            storeB(buf);
            if (tap < 8) loadB(tap + 1, c0);
            else if (ic + 1 < NC) loadB(0, c0 + 32);
            if (tap == 7 && ic + 1 < NC) loadA(c0 + 32);
            __syncthreads();

            const int dy = tap / 3 - 1, dx = tap % 3 - 1;
            const int arow = (warp_m + dy + 1) * 34 + dx + 1;
            #pragma unroll
            for (int ks = 0; ks < 4; ks++) {
                const int k0 = ks * 8 + (lane & 3);
                uint32_t bf[4][2];
                #pragma unroll
                for (int nt = 0; nt < 4; nt++) {
                    int n = warp_n * 32 + nt * 8 + (lane >> 2);
                    bf[nt][0] = s_b[buf][n * 36 + k0];
                    bf[nt][1] = s_b[buf][n * 36 + k0 + 4];
                }
                uint32_t af[2][4];
                #pragma unroll
                for (int mt = 0; mt < 2; mt++) {
                    int hp0 = arow + mt * 16 + (lane >> 2);
                    af[mt][0] = s_a[hp0 * 36 + k0];
                    af[mt][1] = s_a[(hp0 + 8) * 36 + k0];
                    af[mt][2] = s_a[hp0 * 36 + k0 + 4];
                    af[mt][3] = s_a[(hp0 + 8) * 36 + k0 + 4];
                }
                #pragma unroll
                for (int mt = 0; mt < 2; mt++)
                    #pragma unroll
                    for (int nt = 0; nt < 4; nt++)
                        mma_16n8k8(acc[mt][nt], af[mt], bf[nt]);
            }
        }
    }

    // epilogue
    const int gy = gy0 + warp_m;
    float sum0[4], sum1[4];
    #pragma unroll
    for (int nt = 0; nt < 4; nt++) { sum0[nt] = 0.f; sum1[nt] = 0.f; }

    #pragma unroll
    for (int mt = 0; mt < 2; mt++) {
        #pragma unroll
        for (int hi = 0; hi < 2; hi++) {
            int px = mt * 16 + (lane >> 2) + hi * 8;
            size_t pixidx = (size_t)gy * WW + gx0 + px;
            #pragma unroll
            for (int nt = 0; nt < 4; nt++) {
                int oc = warp_n * 32 + nt * 8 + 2 * (lane & 3);
                float v0 = acc[mt][nt][hi * 2 + 0] + s_bias[oc];
                float v1 = acc[mt][nt][hi * 2 + 1] + s_bias[oc + 1];
                if (FINAL) {
                    dout[((size_t)b * GC + oc) * HW + pixidx]     = 0.2f * v0 + inb[pixidx * CTOT + oc];
                    dout[((size_t)b * GC + oc + 1) * HW + pixidx] = 0.2f * v1 + inb[pixidx * CTOT + oc + 1];
                } else {
                    v0 = v0 >= 0.f ? v0 : 0.2f * v0;
                    v1 = v1 >= 0.f ? v1 : 0.2f * v1;
                    *(float2*)&g_concat[((size_t)b * HW + pixidx) * CTOT + out_ch_off + oc] =
                        make_float2(v0, v1);
                    sum0[nt] += v0;
                    sum1[nt] += v1;
                }
            }
        }
    }

    if (!FINAL) {
        // reduce over lane>>2 groups (pixels), keep lane&3 (oc selector)
        #pragma unroll
        for (int nt = 0; nt < 4; nt++) {
            #pragma unroll
            for (int off = 16; off >= 4; off >>= 1) {
                sum0[nt] += __shfl_xor_sync(0xFFFFFFFFu, sum0[nt], off);
                sum1[nt] += __shfl_xor_sync(0xFFFFFFFFu, sum1[nt], off);
            }
        }
        if (lane < 4) {
            #pragma unroll
            for (int nt = 0; nt < 4; nt++) {
                int chl = warp_n * 32 + nt * 8 + 2 * lane;
                s_red[warp_m][chl]     = sum0[nt];
                s_red[warp_m][chl + 1] = sum1[nt];
            }
        }
        __syncthreads();
        if (t < 64) {
            int tile = blockIdx.y * 3 + blockIdx.x;
            g_partial[((size_t)b * 144 + tile) * 64 + t] =
                s_red[0][t] + s_red[1][t] + s_red[2][t] + s_red[3][t];
        }
    }
}

// ---------------------------------------------------------------------------
// Host orchestration
// ---------------------------------------------------------------------------
extern "C" void kernel_launch(void* const* d_in, const int* in_sizes, int n_in,
                              void* d_out, int out_size) {
    const float* x = (const float*)d_in[0];
    const float *W[5], *Bv[5], *A1[5], *Ab1[5], *A2[5], *Ab2[5];
    for (int i = 0; i < 5; i++) {
        W[i]   = (const float*)d_in[1 + 6 * i + 0];
        Bv[i]  = (const float*)d_in[1 + 6 * i + 1];
        A1[i]  = (const float*)d_in[1 + 6 * i + 2];
        Ab1[i] = (const float*)d_in[1 + 6 * i + 3];
        A2[i]  = (const float*)d_in[1 + 6 * i + 4];
        Ab2[i] = (const float*)d_in[1 + 6 * i + 5];
    }
    float* out = (float*)d_out;

    dim3 cgrid(3, 24, NB);

    copyx_t<<<dim3(144, NB), 256>>>(x);
    reduce_gap<<<NB, 256>>>(144, 0);

    // Layer 1 (cin=64)
    attn_kernel<64><<<NB, 128>>>(A1[0], Ab1[0], A2[0], Ab2[0], Bv[0]);
    mix2_kernel<64><<<(NB * 9 * GC * 64 + 255) / 256, 256>>>(W[0]);
    conv_mma<64, false><<<cgrid, 256>>>(nullptr, 64);
    reduce_gap<<<NB, 256>>>(72, 64);

    // Layer 2 (cin=128)
    attn_kernel<128><<<NB, 128>>>(A1[1], Ab1[1], A2[1], Ab2[1], Bv[1]);
    mix2_kernel<128><<<(NB * 9 * GC * 128 + 255) / 256, 256>>>(W[1]);
    conv_mma<128, false><<<cgrid, 256>>>(nullptr, 128);
    reduce_gap<<<NB, 256>>>(72, 128);

    // Layer 3 (cin=192)
    attn_kernel<192><<<NB, 128>>>(A1[2], Ab1[2], A2[2], Ab2[2], Bv[2]);
    mix2_kernel<192><<<(NB * 9 * GC * 192 + 255) / 256, 256>>>(W[2]);
    conv_mma<192, false><<<cgrid, 256>>>(nullptr, 192);
    reduce_gap<<<NB, 256>>>(72, 192);

    // Layer 4 (cin=256)
    attn_kernel<256><<<NB, 128>>>(A1[3], Ab1[3], A2[3], Ab2[3], Bv[3]);
    mix2_kernel<256><<<(NB * 9 * GC * 256 + 255) / 256, 256>>>(W[3]);
    conv_mma<256, false><<<cgrid, 256>>>(nullptr, 256);
    reduce_gap<<<NB, 256>>>(72, 256);

    // Layer 5 (cin=320) -> final output with residual
    attn_kernel<320><<<NB, 128>>>(A1[4], Ab1[4], A2[4], Ab2[4], Bv[4]);
    mix2_kernel<320><<<(NB * 9 * GC * 320 + 255) / 256, 256>>>(W[4]);
    conv_mma<320, true><<<cgrid, 256>>>(out, 0);
}

// round 6
// speedup vs baseline: 3.3465x; 1.0029x over previous
#include <cuda_runtime.h>
#include <cuda_bf16.h>
#include <cstdint>
#include <math.h>

#define NB   16
#define NF   64
#define GC   64
#define KK   8
#define HH   96
#define WW   96
#define HW   (HH*WW)
#define CTOT 320

// ---------------------------------------------------------------------------
// Scratch
// ---------------------------------------------------------------------------
__device__ float g_concat[(size_t)NB * HW * CTOT];       // NHWC: [b][pix][c]
__device__ float g_pooled[NB * CTOT];                    // per-channel means
__device__ float g_attn[NB * KK];
__device__ float g_bk[NB * GC];
__device__ float g_wk2[(size_t)NB * 9 * GC * CTOT];      // [b][tap][oc][c]
__device__ float g_partial[(size_t)NB * 144 * 64];       // GAP partials per tile

// ---------------------------------------------------------------------------
// NCHW -> NHWC transpose of input x into g_concat channels [0,64), fused GAP
// partials. grid (144, 16), block 256.
// ---------------------------------------------------------------------------
__global__ void copyx_t(const float* __restrict__ x) {
    __shared__ float sm[64][65];
    __shared__ float red[4][64];
    int b = blockIdx.y;
    int p0 = blockIdx.x * 64;
    int t = threadIdx.x;
    #pragma unroll
    for (int i = 0; i < 16; i++) {
        int idx = t + i * 256;
        int c = idx >> 6, pl = idx & 63;
        sm[c][pl] = x[((size_t)b * 64 + c) * HW + p0 + pl];
    }
    __syncthreads();
    const int c = t & 63;
    float s = 0.f;
    #pragma unroll
    for (int i = 0; i < 16; i++) {
        int pl = (t >> 6) + 4 * i;
        float v = sm[c][pl];
        g_concat[((size_t)b * HW + p0 + pl) * CTOT + c] = v;
        s += v;
    }
    red[t >> 6][c] = s;
    __syncthreads();
    if (t < 64)
        g_partial[((size_t)b * 144 + blockIdx.x) * 64 + t] =
            red[0][t] + red[1][t] + red[2][t] + red[3][t];
}

// ---------------------------------------------------------------------------
// Reduce GAP partials -> g_pooled means. grid(NB), block 256.
// ---------------------------------------------------------------------------
__global__ void reduce_gap(int ntiles, int ch_off) {
    int b = blockIdx.x;
    int t = threadIdx.x;
    int ch = t & 63, grp = t >> 6;
    float s = 0.f;
    for (int tile = grp; tile < ntiles; tile += 4)
        s += g_partial[((size_t)b * 144 + tile) * 64 + ch];
    __shared__ float red[4][64];
    red[grp][ch] = s;
    __syncthreads();
    if (t < 64)
        g_pooled[b * CTOT + ch_off + t] =
            (red[0][t] + red[1][t] + red[2][t] + red[3][t]) * (1.f / (float)HW);
}

// ---------------------------------------------------------------------------
// Attention MLP per sample
// ---------------------------------------------------------------------------
template <int CIN>
__global__ void attn_kernel(const float* __restrict__ aw1, const float* __restrict__ ab1,
                            const float* __restrict__ aw2, const float* __restrict__ ab2,
                            const float* __restrict__ bvec) {
    const int HID = CIN / 4;
    int b = blockIdx.x;
    int t = threadIdx.x;
    __shared__ float sp[CIN];
    __shared__ float sh[HID];
    __shared__ float sl[KK];
    __shared__ float sa[KK];

    for (int i = t; i < CIN; i += 128) sp[i] = g_pooled[b * CTOT + i];
    __syncthreads();
    if (t < HID) {
        float s = ab1[t];
        const float* row = aw1 + (size_t)t * CIN;
        for (int c = 0; c < CIN; c++) s += row[c] * sp[c];
        sh[t] = s > 0.f ? s : 0.f;
    }
    __syncthreads();
    if (t < KK) {
        float s = ab2[t];
        const float* row = aw2 + (size_t)t * HID;
        for (int j = 0; j < HID; j++) s += row[j] * sh[j];
        sl[t] = s;
    }
    __syncthreads();
    if (t == 0) {
        float m = sl[0];
        for (int k = 1; k < KK; k++) m = fmaxf(m, sl[k]);
        float den = 0.f;
        for (int k = 0; k < KK; k++) { float e = expf(sl[k] - m); sa[k] = e; den += e; }
        float inv = 1.f / den;
        for (int k = 0; k < KK; k++) { sa[k] *= inv; g_attn[b * KK + k] = sa[k]; }
    }
    __syncthreads();
    if (t < GC) {
        float s = 0.f;
        #pragma unroll
        for (int k = 0; k < KK; k++) s += sa[k] * bvec[k * GC + t];
        g_bk[b * GC + t] = s;
    }
}

// ---------------------------------------------------------------------------
// Mix expert weights into tap-major layout: g_wk2[b][tap][oc][c]
// ---------------------------------------------------------------------------
template <int CIN>
__global__ void mix2_kernel(const float* __restrict__ w) {
    const int per_b = 9 * GC * CIN;
    int i = blockIdx.x * 256 + threadIdx.x;
    if (i >= NB * per_b) return;
    int b = i / per_b;
    int r = i - b * per_b;
    int tap = r % 9;
    int cc  = (r / 9) % CIN;
    int oc  = r / (9 * CIN);
    float s = 0.f;
    #pragma unroll
    for (int k = 0; k < KK; k++)
        s += g_attn[b * KK + k] * w[(((size_t)k * GC + oc) * CIN + cc) * 9 + tap];
    g_wk2[(((size_t)b * 9 + tap) * GC + oc) * CIN + cc] = s;
}

// ---------------------------------------------------------------------------
// tf32 mma.sync implicit-GEMM conv with register prefetch + fused GAP partials.
// CTA: 128 pixels (4 rows x 32 cols) x 64 oc. 8 warps = 4(m) x 2(n), each 32x32.
// grid (3, 24, NB), block 256.
// ---------------------------------------------------------------------------
__device__ __forceinline__ void mma_16n8k8(float* c, const uint32_t* a, const uint32_t* b) {
    asm volatile(
        "mma.sync.aligned.m16n8k8.row.col.f32.tf32.tf32.f32 "
        "{%0,%1,%2,%3}, {%4,%5,%6,%7}, {%8,%9}, {%0,%1,%2,%3};"
        : "+f"(c[0]), "+f"(c[1]), "+f"(c[2]), "+f"(c[3])
        : "r"(a[0]), "r"(a[1]), "r"(a[2]), "r"(a[3]), "r"(b[0]), "r"(b[1]));
}

__device__ __forceinline__ uint32_t f2tf32(float v) {
    uint32_t u;
    asm("cvt.rna.tf32.f32 %0, %1;" : "=r"(u) : "f"(v));
    return u;
}

template <int CIN, bool FINAL>
__global__ __launch_bounds__(256, 2)
void conv_mma(float* __restrict__ dout, int out_ch_off) {
    __shared__ uint32_t s_a[204 * 36];        // 6x34 halo pixels x 32ch (pad 36)
    __shared__ uint32_t s_b[2][64 * 36];      // double-buffered 64oc x 32ch
    __shared__ float s_bias[64];
    __shared__ float s_red[4][64];

    const int t = threadIdx.x;
    const int lane = t & 31;
    const int wid = t >> 5;
    const int warp_m = wid & 3;
    const int warp_n = wid >> 2;
    const int gx0 = blockIdx.x * 32;
    const int gy0 = blockIdx.y * 4;
    const int b = blockIdx.z;
    const int NC = CIN / 32;

    const float* inb = g_concat + (size_t)b * HW * CTOT;
    const float* wkb = g_wk2 + (size_t)b * (9 * GC * CIN);

    if (t < 64) s_bias[t] = g_bk[b * GC + t];

    float acc[2][4][4];
    #pragma unroll
    for (int mt = 0; mt < 2; mt++)
        #pragma unroll
        for (int nt = 0; nt < 4; nt++)
            #pragma unroll
            for (int q = 0; q < 4; q++) acc[mt][nt][q] = 0.f;

    float4 pfA[7];
    float4 pfB0, pfB1;

    // ---- prefetch helpers ----
    auto loadA = [&](int c0) {
        #pragma unroll
        for (int k = 0; k < 7; k++) {
            int i = t + k * 256;
            float4 v = make_float4(0.f, 0.f, 0.f, 0.f);
            if (i < 1632) {
                int pix = i >> 3, q = i & 7;
                int r = pix / 34, cc = pix - r * 34;
                int gy = gy0 + r - 1, gx = gx0 + cc - 1;
                if ((unsigned)gy < HH && (unsigned)gx < WW)
                    v = *(const float4*)(inb + (size_t)(gy * WW + gx) * CTOT + c0 + q * 4);
            }
            pfA[k] = v;
        }
    };
    auto storeA = [&]() {
        #pragma unroll
        for (int k = 0; k < 7; k++) {
            int i = t + k * 256;
            if (i < 1632) {
                int pix = i >> 3, q = i & 7;
                uint4 u;
                u.x = f2tf32(pfA[k].x); u.y = f2tf32(pfA[k].y);
                u.z = f2tf32(pfA[k].z); u.w = f2tf32(pfA[k].w);
                *(uint4*)&s_a[pix * 36 + q * 4] = u;
            }
        }
    };
    auto loadB = [&](int tap, int c0) {
        int oc0 = t >> 3, q0 = t & 7;
        pfB0 = *(const float4*)(wkb + ((size_t)tap * GC + oc0) * CIN + c0 + q0 * 4);
        int j1 = t + 256;
        int oc1 = j1 >> 3, q1 = j1 & 7;
        pfB1 = *(const float4*)(wkb + ((size_t)tap * GC + oc1) * CIN + c0 + q1 * 4);
    };
    auto storeB = [&](int buf) {
        uint4 u;
        u.x = f2tf32(pfB0.x); u.y = f2tf32(pfB0.y); u.z = f2tf32(pfB0.z); u.w = f2tf32(pfB0.w);
        *(uint4*)&s_b[buf][(t >> 3) * 36 + (t & 7) * 4] = u;
        int j1 = t + 256;
        u.x = f2tf32(pfB1.x); u.y = f2tf32(pfB1.y); u.z = f2tf32(pfB1.z); u.w = f2tf32(pfB1.w);
        *(uint4*)&s_b[buf][(j1 >> 3) * 36 + (j1 & 7) * 4] = u;
    };

    loadA(0);
    loadB(0, 0);

    #pragma unroll 1
    for (int ic = 0; ic < NC; ic++) {
        const int c0 = ic * 32;
        __syncthreads();          // prior chunk's s_a readers done
        storeA();
        #pragma unroll 1
        for (int tap = 0; tap < 9; tap++) {
            const int buf = tap & 1;
            storeB(buf);
            if (tap < 8) loadB(tap + 1, c0);
            else if (ic + 1 < NC) loadB(0, c0 + 32);
            if (tap == 7 && ic + 1 < NC) loadA(c0 + 32);
            __syncthreads();

            const int dy = tap / 3 - 1, dx = tap % 3 - 1;
            const int arow = (warp_m + dy + 1) * 34 + dx + 1;
            #pragma unroll
            for (int ks = 0; ks < 4; ks++) {
                const int k0 = ks * 8 + (lane & 3);
                uint32_t bf[4][2];
                #pragma unroll
                for (int nt = 0; nt < 4; nt++) {
                    int n = warp_n * 32 + nt * 8 + (lane >> 2);
                    bf[nt][0] = s_b[buf][n * 36 + k0];
                    bf[nt][1] = s_b[buf][n * 36 + k0 + 4];
                }
                uint32_t af[2][4];
                #pragma unroll
                for (int mt = 0; mt < 2; mt++) {
                    int hp0 = arow + mt * 16 + (lane >> 2);
                    af[mt][0] = s_a[hp0 * 36 + k0];
                    af[mt][1] = s_a[(hp0 + 8) * 36 + k0];
                    af[mt][2] = s_a[hp0 * 36 + k0 + 4];
                    af[mt][3] = s_a[(hp0 + 8) * 36 + k0 + 4];
                }
                #pragma unroll
                for (int mt = 0; mt < 2; mt++)
                    #pragma unroll
                    for (int nt = 0; nt < 4; nt++)
                        mma_16n8k8(acc[mt][nt], af[mt], bf[nt]);
            }
        }
    }

    // epilogue
    const int gy = gy0 + warp_m;
    float sum0[4], sum1[4];
    #pragma unroll
    for (int nt = 0; nt < 4; nt++) { sum0[nt] = 0.f; sum1[nt] = 0.f; }

    #pragma unroll
    for (int mt = 0; mt < 2; mt++) {
        #pragma unroll
        for (int hi = 0; hi < 2; hi++) {
            int px = mt * 16 + (lane >> 2) + hi * 8;
            size_t pixidx = (size_t)gy * WW + gx0 + px;
            #pragma unroll
            for (int nt = 0; nt < 4; nt++) {
                int oc = warp_n * 32 + nt * 8 + 2 * (lane & 3);
                float v0 = acc[mt][nt][hi * 2 + 0] + s_bias[oc];
                float v1 = acc[mt][nt][hi * 2 + 1] + s_bias[oc + 1];
                if (FINAL) {
                    dout[((size_t)b * GC + oc) * HW + pixidx]     = 0.2f * v0 + inb[pixidx * CTOT + oc];
                    dout[((size_t)b * GC + oc + 1) * HW + pixidx] = 0.2f * v1 + inb[pixidx * CTOT + oc + 1];
                } else {
                    v0 = v0 >= 0.f ? v0 : 0.2f * v0;
                    v1 = v1 >= 0.f ? v1 : 0.2f * v1;
                    *(float2*)&g_concat[((size_t)b * HW + pixidx) * CTOT + out_ch_off + oc] =
                        make_float2(v0, v1);
                    sum0[nt] += v0;
                    sum1[nt] += v1;
                }
            }
        }
    }

    if (!FINAL) {
        // reduce over lane>>2 groups (pixels), keep lane&3 (oc selector)
        #pragma unroll
        for (int nt = 0; nt < 4; nt++) {
            #pragma unroll
            for (int off = 16; off >= 4; off >>= 1) {
                sum0[nt] += __shfl_xor_sync(0xFFFFFFFFu, sum0[nt], off);
                sum1[nt] += __shfl_xor_sync(0xFFFFFFFFu, sum1[nt], off);
            }
        }
        if (lane < 4) {
            #pragma unroll
            for (int nt = 0; nt < 4; nt++) {
                int chl = warp_n * 32 + nt * 8 + 2 * lane;
                s_red[warp_m][chl]     = sum0[nt];
                s_red[warp_m][chl + 1] = sum1[nt];
            }
        }
        __syncthreads();
        if (t < 64) {
            int tile = blockIdx.y * 3 + blockIdx.x;
            g_partial[((size_t)b * 144 + tile) * 64 + t] =
                s_red[0][t] + s_red[1][t] + s_red[2][t] + s_red[3][t];
        }
    }
}

// ---------------------------------------------------------------------------
// Host orchestration
// ---------------------------------------------------------------------------
extern "C" void kernel_launch(void* const* d_in, const int* in_sizes, int n_in,
                              void* d_out, int out_size) {
    const float* x = (const float*)d_in[0];
    const float *W[5], *Bv[5], *A1[5], *Ab1[5], *A2[5], *Ab2[5];
    for (int i = 0; i < 5; i++) {
        W[i]   = (const float*)d_in[1 + 6 * i + 0];
        Bv[i]  = (const float*)d_in[1 + 6 * i + 1];
        A1[i]  = (const float*)d_in[1 + 6 * i + 2];
        Ab1[i] = (const float*)d_in[1 + 6 * i + 3];
        A2[i]  = (const float*)d_in[1 + 6 * i + 4];
        Ab2[i] = (const float*)d_in[1 + 6 * i + 5];
    }
    float* out = (float*)d_out;

    dim3 cgrid(3, 24, NB);

    copyx_t<<<dim3(144, NB), 256>>>(x);
    reduce_gap<<<NB, 256>>>(144, 0);

    // Layer 1 (cin=64)
    attn_kernel<64><<<NB, 128>>>(A1[0], Ab1[0], A2[0], Ab2[0], Bv[0]);
    mix2_kernel<64><<<(NB * 9 * GC * 64 + 255) / 256, 256>>>(W[0]);
    conv_mma<64, false><<<cgrid, 256>>>(nullptr, 64);
    reduce_gap<<<NB, 256>>>(72, 64);

    // Layer 2 (cin=128)
    attn_kernel<128><<<NB, 128>>>(A1[1], Ab1[1], A2[1], Ab2[1], Bv[1]);
    mix2_kernel<128><<<(NB * 9 * GC * 128 + 255) / 256, 256>>>(W[1]);
    conv_mma<128, false><<<cgrid, 256>>>(nullptr, 128);
    reduce_gap<<<NB, 256>>>(72, 128);

    // Layer 3 (cin=192)
    attn_kernel<192><<<NB, 128>>>(A1[2], Ab1[2], A2[2], Ab2[2], Bv[2]);
    mix2_kernel<192><<<(NB * 9 * GC * 192 + 255) / 256, 256>>>(W[2]);
    conv_mma<192, false><<<cgrid, 256>>>(nullptr, 192);
    reduce_gap<<<NB, 256>>>(72, 192);

    // Layer 4 (cin=256)
    attn_kernel<256><<<NB, 128>>>(A1[3], Ab1[3], A2[3], Ab2[3], Bv[3]);
    mix2_kernel<256><<<(NB * 9 * GC * 256 + 255) / 256, 256>>>(W[3]);
    conv_mma<256, false><<<cgrid, 256>>>(nullptr, 256);
    reduce_gap<<<NB, 256>>>(72, 256);

    // Layer 5 (cin=320) -> final output with residual
    attn_kernel<320><<<NB, 128>>>(A1[4], Ab1[4], A2[4], Ab2[4], Bv[4]);
    mix2_kernel<320><<<(NB * 9 * GC * 320 + 255) / 256, 256>>>(W[4]);
    conv_mma<320, true><<<cgrid, 256>>>(out, 0);
}

// round 7
// speedup vs baseline: 5.0651x; 1.5136x over previous
#include <cuda_runtime.h>
#include <cuda_fp16.h>
#include <cstdint>
#include <math.h>

#define NB   16
#define NF   64
#define GC   64
#define KK   8
#define HH   96
#define WW   96
#define HW   (HH*WW)
#define CTOT 320

// ---------------------------------------------------------------------------
// Scratch
// ---------------------------------------------------------------------------
__device__ float g_concat[(size_t)NB * HW * CTOT];       // NHWC: [b][pix][c]
__device__ float g_pooled[NB * CTOT];
__device__ float g_attn[NB * KK];
__device__ float g_bk[NB * GC];
__device__ float g_wk2[(size_t)NB * 9 * GC * CTOT];      // [b][tap][oc][c]
__device__ float g_partial[(size_t)NB * 144 * 64];       // GAP partials per tile

// ---------------------------------------------------------------------------
// NCHW -> NHWC transpose of input x, fused GAP partials. grid(144,16), 256.
// ---------------------------------------------------------------------------
__global__ void copyx_t(const float* __restrict__ x) {
    __shared__ float sm[64][65];
    __shared__ float red[4][64];
    int b = blockIdx.y;
    int p0 = blockIdx.x * 64;
    int t = threadIdx.x;
    #pragma unroll
    for (int i = 0; i < 16; i++) {
        int idx = t + i * 256;
        int c = idx >> 6, pl = idx & 63;
        sm[c][pl] = x[((size_t)b * 64 + c) * HW + p0 + pl];
    }
    __syncthreads();
    const int c = t & 63;
    float s = 0.f;
    #pragma unroll
    for (int i = 0; i < 16; i++) {
        int pl = (t >> 6) + 4 * i;
        float v = sm[c][pl];
        g_concat[((size_t)b * HW + p0 + pl) * CTOT + c] = v;
        s += v;
    }
    red[t >> 6][c] = s;
    __syncthreads();
    if (t < 64)
        g_partial[((size_t)b * 144 + blockIdx.x) * 64 + t] =
            red[0][t] + red[1][t] + red[2][t] + red[3][t];
}

// ---------------------------------------------------------------------------
// Reduce GAP partials -> g_pooled means. grid(NB), block 256.
// ---------------------------------------------------------------------------
__global__ void reduce_gap(int ntiles, int ch_off) {
    int b = blockIdx.x;
    int t = threadIdx.x;
    int ch = t & 63, grp = t >> 6;
    float s = 0.f;
    for (int tile = grp; tile < ntiles; tile += 4)
        s += g_partial[((size_t)b * 144 + tile) * 64 + ch];
    __shared__ float red[4][64];
    red[grp][ch] = s;
    __syncthreads();
    if (t < 64)
        g_pooled[b * CTOT + ch_off + t] =
            (red[0][t] + red[1][t] + red[2][t] + red[3][t]) * (1.f / (float)HW);
}

// ---------------------------------------------------------------------------
// Attention MLP per sample
// ---------------------------------------------------------------------------
template <int CIN>
__global__ void attn_kernel(const float* __restrict__ aw1, const float* __restrict__ ab1,
                            const float* __restrict__ aw2, const float* __restrict__ ab2,
                            const float* __restrict__ bvec) {
    const int HID = CIN / 4;
    int b = blockIdx.x;
    int t = threadIdx.x;
    __shared__ float sp[CIN];
    __shared__ float sh[HID];
    __shared__ float sl[KK];
    __shared__ float sa[KK];

    for (int i = t; i < CIN; i += 128) sp[i] = g_pooled[b * CTOT + i];
    __syncthreads();
    if (t < HID) {
        float s = ab1[t];
        const float* row = aw1 + (size_t)t * CIN;
        for (int c = 0; c < CIN; c++) s += row[c] * sp[c];
        sh[t] = s > 0.f ? s : 0.f;
    }
    __syncthreads();
    if (t < KK) {
        float s = ab2[t];
        const float* row = aw2 + (size_t)t * HID;
        for (int j = 0; j < HID; j++) s += row[j] * sh[j];
        sl[t] = s;
    }
    __syncthreads();
    if (t == 0) {
        float m = sl[0];
        for (int k = 1; k < KK; k++) m = fmaxf(m, sl[k]);
        float den = 0.f;
        for (int k = 0; k < KK; k++) { float e = expf(sl[k] - m); sa[k] = e; den += e; }
        float inv = 1.f / den;
        for (int k = 0; k < KK; k++) { sa[k] *= inv; g_attn[b * KK + k] = sa[k]; }
    }
    __syncthreads();
    if (t < GC) {
        float s = 0.f;
        #pragma unroll
        for (int k = 0; k < KK; k++) s += sa[k] * bvec[k * GC + t];
        g_bk[b * GC + t] = s;
    }
}

// ---------------------------------------------------------------------------
// Mix expert weights into tap-major layout: g_wk2[b][tap][oc][c]
// ---------------------------------------------------------------------------
template <int CIN>
__global__ void mix2_kernel(const float* __restrict__ w) {
    const int per_b = 9 * GC * CIN;
    int i = blockIdx.x * 256 + threadIdx.x;
    if (i >= NB * per_b) return;
    int b = i / per_b;
    int r = i - b * per_b;
    int tap = r % 9;
    int cc  = (r / 9) % CIN;
    int oc  = r / (9 * CIN);
    float s = 0.f;
    #pragma unroll
    for (int k = 0; k < KK; k++)
        s += g_attn[b * KK + k] * w[(((size_t)k * GC + oc) * CIN + cc) * 9 + tap];
    g_wk2[(((size_t)b * 9 + tap) * GC + oc) * CIN + cc] = s;
}

// ---------------------------------------------------------------------------
// fp16 mma.sync (m16n8k16) implicit-GEMM conv, ldmatrix operand loads,
// register prefetch, fused GAP partials.
// CTA: 128 pixels (4 rows x 32 cols) x 64 oc. 8 warps = 4(m) x 2(n), each 32x32.
// grid (3, 24, NB), block 256.
// ---------------------------------------------------------------------------
#define APAD 40   // row stride in halves (80B): ldmatrix hits all 32 banks once

__device__ __forceinline__ void mma_16816(float* c, const uint32_t* a, const uint32_t* b) {
    asm volatile(
        "mma.sync.aligned.m16n8k16.row.col.f32.f16.f16.f32 "
        "{%0,%1,%2,%3}, {%4,%5,%6,%7}, {%8,%9}, {%0,%1,%2,%3};"
        : "+f"(c[0]), "+f"(c[1]), "+f"(c[2]), "+f"(c[3])
        : "r"(a[0]), "r"(a[1]), "r"(a[2]), "r"(a[3]), "r"(b[0]), "r"(b[1]));
}

__device__ __forceinline__ void ldsm_x4(uint32_t* r, uint32_t saddr) {
    asm volatile("ldmatrix.sync.aligned.m8n8.x4.shared.b16 {%0,%1,%2,%3}, [%4];"
                 : "=r"(r[0]), "=r"(r[1]), "=r"(r[2]), "=r"(r[3]) : "r"(saddr));
}

__device__ __forceinline__ uint32_t pack_h2(float a, float b) {
    __half2 h = __floats2half2_rn(a, b);
    return *(uint32_t*)&h;
}

template <int CIN, bool FINAL>
__global__ __launch_bounds__(256, 2)
void conv_mma(float* __restrict__ dout, int out_ch_off) {
    __shared__ uint16_t s_a[204 * APAD];      // 6x34 halo pixels x 32ch fp16
    __shared__ uint16_t s_b[2][64 * APAD];    // double-buffered 64oc x 32ch fp16
    __shared__ float s_bias[64];
    __shared__ float s_red[4][64];

    const int t = threadIdx.x;
    const int lane = t & 31;
    const int wid = t >> 5;
    const int warp_m = wid & 3;
    const int warp_n = wid >> 2;
    const int gx0 = blockIdx.x * 32;
    const int gy0 = blockIdx.y * 4;
    const int b = blockIdx.z;
    const int NC = CIN / 32;

    const uint32_t sa_u = (uint32_t)__cvta_generic_to_shared(s_a);
    const uint32_t sb_u = (uint32_t)__cvta_generic_to_shared(s_b);

    const float* inb = g_concat + (size_t)b * HW * CTOT;
    const float* wkb = g_wk2 + (size_t)b * (9 * GC * CIN);

    if (t < 64) s_bias[t] = g_bk[b * GC + t];

    float acc[2][4][4];
    #pragma unroll
    for (int mt = 0; mt < 2; mt++)
        #pragma unroll
        for (int nt = 0; nt < 4; nt++)
            #pragma unroll
            for (int q = 0; q < 4; q++) acc[mt][nt][q] = 0.f;

    float4 pfA[7];
    float4 pfB0, pfB1;

    auto loadA = [&](int c0) {
        #pragma unroll
        for (int k = 0; k < 7; k++) {
            int i = t + k * 256;
            float4 v = make_float4(0.f, 0.f, 0.f, 0.f);
            if (i < 1632) {
                int pix = i >> 3, q = i & 7;
                int r = pix / 34, cc = pix - r * 34;
                int gy = gy0 + r - 1, gx = gx0 + cc - 1;
                if ((unsigned)gy < HH && (unsigned)gx < WW)
                    v = *(const float4*)(inb + (size_t)(gy * WW + gx) * CTOT + c0 + q * 4);
            }
            pfA[k] = v;
        }
    };
    auto storeA = [&]() {
        #pragma unroll
        for (int k = 0; k < 7; k++) {
            int i = t + k * 256;
            if (i < 1632) {
                int pix = i >> 3, q = i & 7;
                uint2 u = make_uint2(pack_h2(pfA[k].x, pfA[k].y), pack_h2(pfA[k].z, pfA[k].w));
                *(uint2*)&s_a[pix * APAD + q * 4] = u;
            }
        }
    };
    auto loadB = [&](int tap, int c0) {
        int oc0 = t >> 3, q0 = t & 7;
        pfB0 = *(const float4*)(wkb + ((size_t)tap * GC + oc0) * CIN + c0 + q0 * 4);
        int j1 = t + 256;
        int oc1 = j1 >> 3, q1 = j1 & 7;
        pfB1 = *(const float4*)(wkb + ((size_t)tap * GC + oc1) * CIN + c0 + q1 * 4);
    };
    auto storeB = [&](int buf) {
        uint2 u = make_uint2(pack_h2(pfB0.x, pfB0.y), pack_h2(pfB0.z, pfB0.w));
        *(uint2*)&s_b[buf][(t >> 3) * APAD + (t & 7) * 4] = u;
        int j1 = t + 256;
        u = make_uint2(pack_h2(pfB1.x, pfB1.y), pack_h2(pfB1.z, pfB1.w));
        *(uint2*)&s_b[buf][(j1 >> 3) * APAD + (j1 & 7) * 4] = u;
    };

    loadA(0);
    loadB(0, 0);

    #pragma unroll 1
    for (int ic = 0; ic < NC; ic++) {
        const int c0 = ic * 32;
        __syncthreads();
        storeA();
        #pragma unroll 1
        for (int tap = 0; tap < 9; tap++) {
            const int buf = tap & 1;
            storeB(buf);
            if (tap < 8) loadB(tap + 1, c0);
            else if (ic + 1 < NC) loadB(0, c0 + 32);
            if (tap == 7 && ic + 1 < NC) loadA(c0 + 32);
            __syncthreads();

            const int dy = tap / 3 - 1, dx = tap % 3 - 1;
            const int arow = (warp_m + dy + 1) * 34 + dx + 1;
            // per-lane ldmatrix row addressing
            const int a_m  = lane & 15;            // pixel within m16 tile
            const int a_kh = lane >> 4;            // k-half (8 halves)
            const int b_n  = (lane >> 4) * 8 + (lane & 7);   // oc within n16 pair
            const int b_kh = (lane >> 3) & 1;

            #pragma unroll
            for (int k16 = 0; k16 < 2; k16++) {
                uint32_t af[2][4];
                #pragma unroll
                for (int mt = 0; mt < 2; mt++) {
                    uint32_t addr = sa_u + 2 * ((arow + mt * 16 + a_m) * APAD + k16 * 16 + a_kh * 8);
                    ldsm_x4(af[mt], addr);
                }
                uint32_t bf[4][2];
                #pragma unroll
                for (int j = 0; j < 2; j++) {
                    uint32_t r[4];
                    int n = warp_n * 32 + j * 16 + b_n;
                    uint32_t addr = sb_u + buf * (64 * APAD * 2) +
                                    2 * (n * APAD + k16 * 16 + b_kh * 8);
                    ldsm_x4(r, addr);
                    bf[j * 2][0] = r[0]; bf[j * 2][1] = r[1];
                    bf[j * 2 + 1][0] = r[2]; bf[j * 2 + 1][1] = r[3];
                }
                #pragma unroll
                for (int mt = 0; mt < 2; mt++)
                    #pragma unroll
                    for (int nt = 0; nt < 4; nt++)
                        mma_16816(acc[mt][nt], af[mt], bf[nt]);
            }
        }
    }

    // epilogue (+ fused GAP partials)
    const int gy = gy0 + warp_m;
    float sum0[4], sum1[4];
    #pragma unroll
    for (int nt = 0; nt < 4; nt++) { sum0[nt] = 0.f; sum1[nt] = 0.f; }

    #pragma unroll
    for (int mt = 0; mt < 2; mt++) {
        #pragma unroll
        for (int hi = 0; hi < 2; hi++) {
            int px = mt * 16 + (lane >> 2) + hi * 8;
            size_t pixidx = (size_t)gy * WW + gx0 + px;
            #pragma unroll
            for (int nt = 0; nt < 4; nt++) {
                int oc = warp_n * 32 + nt * 8 + 2 * (lane & 3);
                float v0 = acc[mt][nt][hi * 2 + 0] + s_bias[oc];
                float v1 = acc[mt][nt][hi * 2 + 1] + s_bias[oc + 1];
                if (FINAL) {
                    dout[((size_t)b * GC + oc) * HW + pixidx]     = 0.2f * v0 + inb[pixidx * CTOT + oc];
                    dout[((size_t)b * GC + oc + 1) * HW + pixidx] = 0.2f * v1 + inb[pixidx * CTOT + oc + 1];
                } else {
                    v0 = v0 >= 0.f ? v0 : 0.2f * v0;
                    v1 = v1 >= 0.f ? v1 : 0.2f * v1;
                    *(float2*)&g_concat[((size_t)b * HW + pixidx) * CTOT + out_ch_off + oc] =
                        make_float2(v0, v1);
                    sum0[nt] += v0;
                    sum1[nt] += v1;
                }
            }
        }
    }

    if (!FINAL) {
        #pragma unroll
        for (int nt = 0; nt < 4; nt++) {
            #pragma unroll
            for (int off = 16; off >= 4; off >>= 1) {
                sum0[nt] += __shfl_xor_sync(0xFFFFFFFFu, sum0[nt], off);
                sum1[nt] += __shfl_xor_sync(0xFFFFFFFFu, sum1[nt], off);
            }
        }
        if (lane < 4) {
            #pragma unroll
            for (int nt = 0; nt < 4; nt++) {
                int chl = warp_n * 32 + nt * 8 + 2 * lane;
                s_red[warp_m][chl]     = sum0[nt];
                s_red[warp_m][chl + 1] = sum1[nt];
            }
        }
        __syncthreads();
        if (t < 64) {
            int tile = blockIdx.y * 3 + blockIdx.x;
            g_partial[((size_t)b * 144 + tile) * 64 + t] =
                s_red[0][t] + s_red[1][t] + s_red[2][t] + s_red[3][t];
        }
    }
}

// ---------------------------------------------------------------------------
// Host orchestration
// ---------------------------------------------------------------------------
extern "C" void kernel_launch(void* const* d_in, const int* in_sizes, int n_in,
                              void* d_out, int out_size) {
    const float* x = (const float*)d_in[0];
    const float *W[5], *Bv[5], *A1[5], *Ab1[5], *A2[5], *Ab2[5];
    for (int i = 0; i < 5; i++) {
        W[i]   = (const float*)d_in[1 + 6 * i + 0];
        Bv[i]  = (const float*)d_in[1 + 6 * i + 1];
        A1[i]  = (const float*)d_in[1 + 6 * i + 2];
        Ab1[i] = (const float*)d_in[1 + 6 * i + 3];
        A2[i]  = (const float*)d_in[1 + 6 * i + 4];
        Ab2[i] = (const float*)d_in[1 + 6 * i + 5];
    }
    float* out = (float*)d_out;

    dim3 cgrid(3, 24, NB);

    copyx_t<<<dim3(144, NB), 256>>>(x);
    reduce_gap<<<NB, 256>>>(144, 0);

    // Layer 1 (cin=64)
    attn_kernel<64><<<NB, 128>>>(A1[0], Ab1[0], A2[0], Ab2[0], Bv[0]);
    mix2_kernel<64><<<(NB * 9 * GC * 64 + 255) / 256, 256>>>(W[0]);
    conv_mma<64, false><<<cgrid, 256>>>(nullptr, 64);
    reduce_gap<<<NB, 256>>>(72, 64);

    // Layer 2 (cin=128)
    attn_kernel<128><<<NB, 128>>>(A1[1], Ab1[1], A2[1], Ab2[1], Bv[1]);
    mix2_kernel<128><<<(NB * 9 * GC * 128 + 255) / 256, 256>>>(W[1]);
    conv_mma<128, false><<<cgrid, 256>>>(nullptr, 128);
    reduce_gap<<<NB, 256>>>(72, 128);

    // Layer 3 (cin=192)
    attn_kernel<192><<<NB, 128>>>(A1[2], Ab1[2], A2[2], Ab2[2], Bv[2]);
    mix2_kernel<192><<<(NB * 9 * GC * 192 + 255) / 256, 256>>>(W[2]);
    conv_mma<192, false><<<cgrid, 256>>>(nullptr, 192);
    reduce_gap<<<NB, 256>>>(72, 192);

    // Layer 4 (cin=256)
    attn_kernel<256><<<NB, 128>>>(A1[3], Ab1[3], A2[3], Ab2[3], Bv[3]);
    mix2_kernel<256><<<(NB * 9 * GC * 256 + 255) / 256, 256>>>(W[3]);
    conv_mma<256, false><<<cgrid, 256>>>(nullptr, 256);
    reduce_gap<<<NB, 256>>>(72, 256);

    // Layer 5 (cin=320) -> final output with residual
    attn_kernel<320><<<NB, 128>>>(A1[4], Ab1[4], A2[4], Ab2[4], Bv[4]);
    mix2_kernel<320><<<(NB * 9 * GC * 320 + 255) / 256, 256>>>(W[4]);
    conv_mma<320, true><<<cgrid, 256>>>(out, 0);
}

// round 8
// speedup vs baseline: 6.0359x; 1.1917x over previous
#include <cuda_runtime.h>
#include <cuda_fp16.h>
#include <cstdint>
#include <math.h>

#define NB   16
#define NF   64
#define GC   64
#define KK   8
#define HH   96
#define WW   96
#define HW   (HH*WW)
#define CTOT 320

// ---------------------------------------------------------------------------
// Scratch
// ---------------------------------------------------------------------------
__device__ __half g_concat[(size_t)NB * HW * CTOT];      // NHWC fp16
__device__ float  g_pooled[NB * CTOT];
__device__ float  g_attn[NB * KK];
__device__ float  g_bk[NB * GC];
__device__ __half g_wk2h[(size_t)NB * 9 * GC * CTOT];    // [b][tap][oc][c] fp16
__device__ float  g_partial[(size_t)NB * 144 * 64];      // GAP partials per tile

// ---------------------------------------------------------------------------
// NCHW fp32 -> NHWC fp16 transpose of input x, fused GAP partials (fp32).
// grid (144, 16), block 256.
// ---------------------------------------------------------------------------
__global__ void copyx_t(const float* __restrict__ x) {
    __shared__ float sm[64][65];
    __shared__ float red[4][64];
    int b = blockIdx.y;
    int p0 = blockIdx.x * 64;
    int t = threadIdx.x;
    #pragma unroll
    for (int i = 0; i < 16; i++) {
        int idx = t + i * 256;
        int c = idx >> 6, pl = idx & 63;
        sm[c][pl] = x[((size_t)b * 64 + c) * HW + p0 + pl];
    }
    __syncthreads();
    const int c = t & 63;
    float s = 0.f;
    #pragma unroll
    for (int i = 0; i < 16; i++) {
        int pl = (t >> 6) + 4 * i;
        float v = sm[c][pl];
        g_concat[((size_t)b * HW + p0 + pl) * CTOT + c] = __float2half(v);
        s += v;
    }
    red[t >> 6][c] = s;
    __syncthreads();
    if (t < 64)
        g_partial[((size_t)b * 144 + blockIdx.x) * 64 + t] =
            red[0][t] + red[1][t] + red[2][t] + red[3][t];
}

// ---------------------------------------------------------------------------
// Attention MLP per sample, with fused GAP-partial reduction for the newest
// 64 channels. grid(NB), block 128.
// ---------------------------------------------------------------------------
template <int CIN>
__global__ void attn_kernel(const float* __restrict__ aw1, const float* __restrict__ ab1,
                            const float* __restrict__ aw2, const float* __restrict__ ab2,
                            const float* __restrict__ bvec, int ntiles, int ch_off) {
    const int HID = CIN / 4;
    int b = blockIdx.x;
    int t = threadIdx.x;
    __shared__ float red[2][64];
    __shared__ float sp[CIN];
    __shared__ float sh[HID];
    __shared__ float sl[KK];
    __shared__ float sa[KK];

    // reduce newest GAP partials -> g_pooled[ch_off..ch_off+64)
    {
        int ch = t & 63, grp = t >> 6;
        float s = 0.f;
        for (int tile = grp; tile < ntiles; tile += 2)
            s += g_partial[((size_t)b * 144 + tile) * 64 + ch];
        red[grp][ch] = s;
        __syncthreads();
        if (t < 64)
            g_pooled[b * CTOT + ch_off + t] = (red[0][t] + red[1][t]) * (1.f / (float)HW);
        __syncthreads();
    }

    for (int i = t; i < CIN; i += 128) sp[i] = g_pooled[b * CTOT + i];
    __syncthreads();
    if (t < HID) {
        float s = ab1[t];
        const float* row = aw1 + (size_t)t * CIN;
        for (int c = 0; c < CIN; c++) s += row[c] * sp[c];
        sh[t] = s > 0.f ? s : 0.f;
    }
    __syncthreads();
    if (t < KK) {
        float s = ab2[t];
        const float* row = aw2 + (size_t)t * HID;
        for (int j = 0; j < HID; j++) s += row[j] * sh[j];
        sl[t] = s;
    }
    __syncthreads();
    if (t == 0) {
        float m = sl[0];
        for (int k = 1; k < KK; k++) m = fmaxf(m, sl[k]);
        float den = 0.f;
        for (int k = 0; k < KK; k++) { float e = expf(sl[k] - m); sa[k] = e; den += e; }
        float inv = 1.f / den;
        for (int k = 0; k < KK; k++) { sa[k] *= inv; g_attn[b * KK + k] = sa[k]; }
    }
    __syncthreads();
    if (t < GC) {
        float s = 0.f;
        #pragma unroll
        for (int k = 0; k < KK; k++) s += sa[k] * bvec[k * GC + t];
        g_bk[b * GC + t] = s;
    }
}

// ---------------------------------------------------------------------------
// Mix expert weights -> fp16 tap-major layout g_wk2h[b][tap][oc][c].
// Thread handles 2 consecutive c (coalesced half2 writes).
// ---------------------------------------------------------------------------
template <int CIN>
__global__ void mix2h_kernel(const float* __restrict__ w) {
    const int per_b = 9 * GC * (CIN / 2);
    int i = blockIdx.x * 256 + threadIdx.x;
    if (i >= NB * per_b) return;
    int b = i / per_b;
    int r = i - b * per_b;
    int cc  = (r % (CIN / 2)) * 2;
    int tap = (r / (CIN / 2)) % 9;
    int oc  = r / (9 * (CIN / 2));
    float s0 = 0.f, s1 = 0.f;
    #pragma unroll
    for (int k = 0; k < KK; k++) {
        float a = g_attn[b * KK + k];
        size_t base = (((size_t)k * GC + oc) * CIN + cc) * 9 + tap;
        s0 += a * w[base];
        s1 += a * w[base + 9];
    }
    *(__half2*)&g_wk2h[(((size_t)b * 9 + tap) * GC + oc) * CIN + cc] =
        __floats2half2_rn(s0, s1);
}

// ---------------------------------------------------------------------------
// fp16 mma.sync conv, cp.async whole-chunk double-buffered pipeline.
// CTA: 256 pixels (8 rows x 32 cols) x 64 oc. 8 warps, each 32px x 64oc.
// Stage smem = A halo (340 rows x 40 halves) + B all 9 taps (576 rows x 40).
// grid (3, 12, NB), block 256, dynamic smem 2*73280.
// ---------------------------------------------------------------------------
#define APAD 40
#define A_ROWS 340
#define B_ROWS 576
#define A_BYTES (A_ROWS * APAD * 2)         // 27200
#define STAGE_BYTES (A_BYTES + B_ROWS * APAD * 2)  // 73280
#define CONV_SMEM (2 * STAGE_BYTES)

__device__ __forceinline__ void mma_16816(float* c, const uint32_t* a, const uint32_t* b) {
    asm volatile(
        "mma.sync.aligned.m16n8k16.row.col.f32.f16.f16.f32 "
        "{%0,%1,%2,%3}, {%4,%5,%6,%7}, {%8,%9}, {%0,%1,%2,%3};"
        : "+f"(c[0]), "+f"(c[1]), "+f"(c[2]), "+f"(c[3])
        : "r"(a[0]), "r"(a[1]), "r"(a[2]), "r"(a[3]), "r"(b[0]), "r"(b[1]));
}

__device__ __forceinline__ void ldsm_x4(uint32_t* r, uint32_t saddr) {
    asm volatile("ldmatrix.sync.aligned.m8n8.x4.shared.b16 {%0,%1,%2,%3}, [%4];"
                 : "=r"(r[0]), "=r"(r[1]), "=r"(r[2]), "=r"(r[3]) : "r"(saddr));
}

__device__ __forceinline__ void cp_async16(uint32_t dst, const void* src, int src_sz) {
    asm volatile("cp.async.cg.shared.global [%0], [%1], 16, %2;"
                 :: "r"(dst), "l"(src), "r"(src_sz) : "memory");
}
#define CP_COMMIT() asm volatile("cp.async.commit_group;" ::: "memory")
#define CP_WAIT0()  asm volatile("cp.async.wait_group 0;" ::: "memory")

template <int CIN, bool FINAL>
__global__ __launch_bounds__(256, 1)
void conv_mma(float* __restrict__ dout, const float* __restrict__ xres, int out_ch_off) {
    extern __shared__ __align__(16) char dyn[];
    __shared__ float s_bias[64];
    __shared__ float s_red[8][64];

    const int t = threadIdx.x;
    const int lane = t & 31;
    const int wid = t >> 5;
    const int gx0 = blockIdx.x * 32;
    const int gy0 = blockIdx.y * 8;
    const int b = blockIdx.z;
    const int NC = CIN / 32;

    const uint32_t su = (uint32_t)__cvta_generic_to_shared(dyn);
    const __half* inb = g_concat + (size_t)b * HW * CTOT;
    const __half* wkb = g_wk2h + (size_t)b * (9 * GC * CIN);

    if (t < 64) s_bias[t] = g_bk[b * GC + t];

    float acc[2][8][4];
    #pragma unroll
    for (int mt = 0; mt < 2; mt++)
        #pragma unroll
        for (int nt = 0; nt < 8; nt++)
            #pragma unroll
            for (int q = 0; q < 4; q++) acc[mt][nt][q] = 0.f;

    // issue cp.async for one chunk into a stage
    auto issue_chunk = [&](int c0, int stage) {
        uint32_t sbase = su + stage * STAGE_BYTES;
        // A: 340 halo rows x 4 chunks of 16B
        #pragma unroll
        for (int k = 0; k < 6; k++) {
            int i = t + k * 256;
            if (i < A_ROWS * 4) {
                int row = i >> 2, q = i & 3;
                int r = row / 34, cc = row - r * 34;
                int gy = gy0 + r - 1, gx = gx0 + cc - 1;
                bool ok = ((unsigned)gy < HH) && ((unsigned)gx < WW);
                const __half* src = ok ? (inb + (size_t)(gy * WW + gx) * CTOT + c0 + q * 8)
                                       : inb;
                cp_async16(sbase + (row * APAD + q * 8) * 2, src, ok ? 16 : 0);
            }
        }
        // B: 576 rows (tap*64+oc) x 4 chunks of 16B
        #pragma unroll
        for (int k = 0; k < 9; k++) {
            int i = t + k * 256;
            if (i < B_ROWS * 4) {
                int row = i >> 2, q = i & 3;
                const __half* src = wkb + (size_t)row * CIN + c0 + q * 8;
                cp_async16(sbase + A_BYTES + (row * APAD + q * 8) * 2, src, 16);
            }
        }
    };

    issue_chunk(0, 0);
    CP_COMMIT();

    // ldmatrix lane addressing
    const int a_m  = lane & 15;
    const int a_kh = lane >> 4;
    const int b_n  = (lane >> 4) * 8 + (lane & 7);
    const int b_kh = (lane >> 3) & 1;

    #pragma unroll 1
    for (int ic = 0; ic < NC; ic++) {
        const int s = ic & 1;
        const uint32_t sa_u = su + s * STAGE_BYTES;
        const uint32_t sb_u = sa_u + A_BYTES;

        CP_WAIT0();
        __syncthreads();
        if (ic + 1 < NC) {
            issue_chunk((ic + 1) * 32, s ^ 1);
            CP_COMMIT();
        }

        #pragma unroll 1
        for (int tap = 0; tap < 9; tap++) {
            const int dy = tap / 3 - 1, dx = tap % 3 - 1;
            const int arow = (wid + dy + 1) * 34 + dx + 1;
            const uint32_t btap = sb_u + (tap * 64) * (APAD * 2);
            #pragma unroll
            for (int k16 = 0; k16 < 2; k16++) {
                uint32_t af[2][4];
                #pragma unroll
                for (int mt = 0; mt < 2; mt++) {
                    uint32_t addr = sa_u + 2 * ((arow + mt * 16 + a_m) * APAD + k16 * 16 + a_kh * 8);
                    ldsm_x4(af[mt], addr);
                }
                uint32_t bf[8][2];
                #pragma unroll
                for (int j = 0; j < 4; j++) {
                    uint32_t r[4];
                    int n = j * 16 + b_n;
                    uint32_t addr = btap + 2 * (n * APAD + k16 * 16 + b_kh * 8);
                    ldsm_x4(r, addr);
                    bf[j * 2][0] = r[0]; bf[j * 2][1] = r[1];
                    bf[j * 2 + 1][0] = r[2]; bf[j * 2 + 1][1] = r[3];
                }
                #pragma unroll
                for (int mt = 0; mt < 2; mt++)
                    #pragma unroll
                    for (int nt = 0; nt < 8; nt++)
                        mma_16816(acc[mt][nt], af[mt], bf[nt]);
            }
        }
        __syncthreads();
    }

    // epilogue (+ fused GAP partials)
    const int gy = gy0 + wid;
    float sum0[8], sum1[8];
    #pragma unroll
    for (int nt = 0; nt < 8; nt++) { sum0[nt] = 0.f; sum1[nt] = 0.f; }

    #pragma unroll
    for (int mt = 0; mt < 2; mt++) {
        #pragma unroll
        for (int hi = 0; hi < 2; hi++) {
            int px = mt * 16 + (lane >> 2) + hi * 8;
            size_t pixidx = (size_t)gy * WW + gx0 + px;
            #pragma unroll
            for (int nt = 0; nt < 8; nt++) {
                int oc = nt * 8 + 2 * (lane & 3);
                float v0 = acc[mt][nt][hi * 2 + 0] + s_bias[oc];
                float v1 = acc[mt][nt][hi * 2 + 1] + s_bias[oc + 1];
                if (FINAL) {
                    dout[((size_t)b * GC + oc) * HW + pixidx] =
                        0.2f * v0 + xres[((size_t)b * GC + oc) * HW + pixidx];
                    dout[((size_t)b * GC + oc + 1) * HW + pixidx] =
                        0.2f * v1 + xres[((size_t)b * GC + oc + 1) * HW + pixidx];
                } else {
                    v0 = v0 >= 0.f ? v0 : 0.2f * v0;
                    v1 = v1 >= 0.f ? v1 : 0.2f * v1;
                    *(__half2*)&g_concat[((size_t)b * HW + pixidx) * CTOT + out_ch_off + oc] =
                        __floats2half2_rn(v0, v1);
                    sum0[nt] += v0;
                    sum1[nt] += v1;
                }
            }
        }
    }

    if (!FINAL) {
        #pragma unroll
        for (int nt = 0; nt < 8; nt++) {
            #pragma unroll
            for (int off = 16; off >= 4; off >>= 1) {
                sum0[nt] += __shfl_xor_sync(0xFFFFFFFFu, sum0[nt], off);
                sum1[nt] += __shfl_xor_sync(0xFFFFFFFFu, sum1[nt], off);
            }
        }
        if (lane < 4) {
            #pragma unroll
            for (int nt = 0; nt < 8; nt++) {
                int chl = nt * 8 + 2 * lane;
                s_red[wid][chl]     = sum0[nt];
                s_red[wid][chl + 1] = sum1[nt];
            }
        }
        __syncthreads();
        if (t < 64) {
            int tile = blockIdx.y * 3 + blockIdx.x;
            float s = 0.f;
            #pragma unroll
            for (int wv = 0; wv < 8; wv++) s += s_red[wv][t];
            g_partial[((size_t)b * 144 + tile) * 64 + t] = s;
        }
    }
}

// ---------------------------------------------------------------------------
// Host orchestration
// ---------------------------------------------------------------------------
extern "C" void kernel_launch(void* const* d_in, const int* in_sizes, int n_in,
                              void* d_out, int out_size) {
    const float* x = (const float*)d_in[0];
    const float *W[5], *Bv[5], *A1[5], *Ab1[5], *A2[5], *Ab2[5];
    for (int i = 0; i < 5; i++) {
        W[i]   = (const float*)d_in[1 + 6 * i + 0];
        Bv[i]  = (const float*)d_in[1 + 6 * i + 1];
        A1[i]  = (const float*)d_in[1 + 6 * i + 2];
        Ab1[i] = (const float*)d_in[1 + 6 * i + 3];
        A2[i]  = (const float*)d_in[1 + 6 * i + 4];
        Ab2[i] = (const float*)d_in[1 + 6 * i + 5];
    }
    float* out = (float*)d_out;

    cudaFuncSetAttribute(conv_mma<64,  false>, cudaFuncAttributeMaxDynamicSharedMemorySize, CONV_SMEM);
    cudaFuncSetAttribute(conv_mma<128, false>, cudaFuncAttributeMaxDynamicSharedMemorySize, CONV_SMEM);
    cudaFuncSetAttribute(conv_mma<192, false>, cudaFuncAttributeMaxDynamicSharedMemorySize, CONV_SMEM);
    cudaFuncSetAttribute(conv_mma<256, false>, cudaFuncAttributeMaxDynamicSharedMemorySize, CONV_SMEM);
    cudaFuncSetAttribute(conv_mma<320, true >, cudaFuncAttributeMaxDynamicSharedMemorySize, CONV_SMEM);

    dim3 cgrid(3, 12, NB);

    copyx_t<<<dim3(144, NB), 256>>>(x);

    // Layer 1 (cin=64)
    attn_kernel<64><<<NB, 128>>>(A1[0], Ab1[0], A2[0], Ab2[0], Bv[0], 144, 0);
    mix2h_kernel<64><<<(NB * 9 * GC * 32 + 255) / 256, 256>>>(W[0]);
    conv_mma<64, false><<<cgrid, 256, CONV_SMEM>>>(nullptr, nullptr, 64);

    // Layer 2 (cin=128)
    attn_kernel<128><<<NB, 128>>>(A1[1], Ab1[1], A2[1], Ab2[1], Bv[1], 36, 64);
    mix2h_kernel<128><<<(NB * 9 * GC * 64 + 255) / 256, 256>>>(W[1]);
    conv_mma<128, false><<<cgrid, 256, CONV_SMEM>>>(nullptr, nullptr, 128);

    // Layer 3 (cin=192)
    attn_kernel<192><<<NB, 128>>>(A1[2], Ab1[2], A2[2], Ab2[2], Bv[2], 36, 128);
    mix2h_kernel<192><<<(NB * 9 * GC * 96 + 255) / 256, 256>>>(W[2]);
    conv_mma<192, false><<<cgrid, 256, CONV_SMEM>>>(nullptr, nullptr, 192);

    // Layer 4 (cin=256)
    attn_kernel<256><<<NB, 128>>>(A1[3], Ab1[3], A2[3], Ab2[3], Bv[3], 36, 192);
    mix2h_kernel<256><<<(NB * 9 * GC * 128 + 255) / 256, 256>>>(W[3]);
    conv_mma<256, false><<<cgrid, 256, CONV_SMEM>>>(nullptr, nullptr, 256);

    // Layer 5 (cin=320) -> final output with fp32 residual from original x
    attn_kernel<320><<<NB, 128>>>(A1[4], Ab1[4], A2[4], Ab2[4], Bv[4], 36, 256);
    mix2h_kernel<320><<<(NB * 9 * GC * 160 + 255) / 256, 256>>>(W[4]);
    conv_mma<320, true><<<cgrid, 256, CONV_SMEM>>>(out, x, 0);
}

// round 9
// speedup vs baseline: 6.0416x; 1.0009x over previous
#include <cuda_runtime.h>
#include <cuda_fp16.h>
#include <cstdint>
#include <math.h>

#define NB   16
#define NF   64
#define GC   64
#define KK   8
#define HH   96
#define WW   96
#define HW   (HH*WW)
#define CTOT 320

// ---------------------------------------------------------------------------
// Scratch
// ---------------------------------------------------------------------------
__device__ __half g_concat[(size_t)NB * HW * CTOT];      // NHWC fp16
__device__ float  g_pooled[NB * CTOT];
__device__ float  g_attn[NB * KK];
__device__ float  g_bk[NB * GC];
__device__ __half g_wk2h[(size_t)NB * 9 * GC * CTOT];    // [b][tap][oc][c] fp16
__device__ float  g_partial[(size_t)NB * 144 * 64];      // GAP partials per tile

// ---------------------------------------------------------------------------
// NCHW fp32 -> NHWC fp16 transpose of input x, fused GAP partials (fp32).
// grid (144, 16), block 256.
// ---------------------------------------------------------------------------
__global__ void copyx_t(const float* __restrict__ x) {
    __shared__ float sm[64][65];
    __shared__ float red[4][64];
    int b = blockIdx.y;
    int p0 = blockIdx.x * 64;
    int t = threadIdx.x;
    #pragma unroll
    for (int i = 0; i < 16; i++) {
        int idx = t + i * 256;
        int c = idx >> 6, pl = idx & 63;
        sm[c][pl] = x[((size_t)b * 64 + c) * HW + p0 + pl];
    }
    __syncthreads();
    const int c = t & 63;
    float s = 0.f;
    #pragma unroll
    for (int i = 0; i < 16; i++) {
        int pl = (t >> 6) + 4 * i;
        float v = sm[c][pl];
        g_concat[((size_t)b * HW + p0 + pl) * CTOT + c] = __float2half(v);
        s += v;
    }
    red[t >> 6][c] = s;
    __syncthreads();
    if (t < 64)
        g_partial[((size_t)b * 144 + blockIdx.x) * 64 + t] =
            red[0][t] + red[1][t] + red[2][t] + red[3][t];
}

// ---------------------------------------------------------------------------
// Attention MLP per sample, with fused GAP-partial reduction for the newest
// 64 channels. grid(NB), block 128.
// ---------------------------------------------------------------------------
template <int CIN>
__global__ void attn_kernel(const float* __restrict__ aw1, const float* __restrict__ ab1,
                            const float* __restrict__ aw2, const float* __restrict__ ab2,
                            const float* __restrict__ bvec, int ntiles, int ch_off) {
    const int HID = CIN / 4;
    int b = blockIdx.x;
    int t = threadIdx.x;
    __shared__ float red[2][64];
    __shared__ float sp[CIN];
    __shared__ float sh[HID];
    __shared__ float sl[KK];
    __shared__ float sa[KK];

    // reduce newest GAP partials -> g_pooled[ch_off..ch_off+64)
    {
        int ch = t & 63, grp = t >> 6;
        float s = 0.f;
        for (int tile = grp; tile < ntiles; tile += 2)
            s += g_partial[((size_t)b * 144 + tile) * 64 + ch];
        red[grp][ch] = s;
        __syncthreads();
        if (t < 64)
            g_pooled[b * CTOT + ch_off + t] = (red[0][t] + red[1][t]) * (1.f / (float)HW);
        __syncthreads();
    }

    for (int i = t; i < CIN; i += 128) sp[i] = g_pooled[b * CTOT + i];
    __syncthreads();
    if (t < HID) {
        float s = ab1[t];
        const float* row = aw1 + (size_t)t * CIN;
        for (int c = 0; c < CIN; c++) s += row[c] * sp[c];
        sh[t] = s > 0.f ? s : 0.f;
    }
    __syncthreads();
    if (t < KK) {
        float s = ab2[t];
        const float* row = aw2 + (size_t)t * HID;
        for (int j = 0; j < HID; j++) s += row[j] * sh[j];
        sl[t] = s;
    }
    __syncthreads();
    if (t == 0) {
        float m = sl[0];
        for (int k = 1; k < KK; k++) m = fmaxf(m, sl[k]);
        float den = 0.f;
        for (int k = 0; k < KK; k++) { float e = expf(sl[k] - m); sa[k] = e; den += e; }
        float inv = 1.f / den;
        for (int k = 0; k < KK; k++) { sa[k] *= inv; g_attn[b * KK + k] = sa[k]; }
    }
    __syncthreads();
    if (t < GC) {
        float s = 0.f;
        #pragma unroll
        for (int k = 0; k < KK; k++) s += sa[k] * bvec[k * GC + t];
        g_bk[b * GC + t] = s;
    }
}

// ---------------------------------------------------------------------------
// Mix expert weights -> fp16 tap-major layout g_wk2h[b][tap][oc][c].
// Thread handles 2 consecutive c (coalesced half2 writes).
// ---------------------------------------------------------------------------
template <int CIN>
__global__ void mix2h_kernel(const float* __restrict__ w) {
    const int per_b = 9 * GC * (CIN / 2);
    int i = blockIdx.x * 256 + threadIdx.x;
    if (i >= NB * per_b) return;
    int b = i / per_b;
    int r = i - b * per_b;
    int cc  = (r % (CIN / 2)) * 2;
    int tap = (r / (CIN / 2)) % 9;
    int oc  = r / (9 * (CIN / 2));
    float s0 = 0.f, s1 = 0.f;
    #pragma unroll
    for (int k = 0; k < KK; k++) {
        float a = g_attn[b * KK + k];
        size_t base = (((size_t)k * GC + oc) * CIN + cc) * 9 + tap;
        s0 += a * w[base];
        s1 += a * w[base + 9];
    }
    *(__half2*)&g_wk2h[(((size_t)b * 9 + tap) * GC + oc) * CIN + cc] =
        __floats2half2_rn(s0, s1);
}

// ---------------------------------------------------------------------------
// fp16 mma.sync conv, cp.async whole-chunk double-buffered pipeline.
// CTA: 256 pixels (8 rows x 32 cols) x 64 oc. 8 warps, each 32px x 64oc.
// Stage smem = A halo (340 rows x 40 halves) + B all 9 taps (576 rows x 40).
// grid (3, 12, NB), block 256, dynamic smem 2*73280.
// ---------------------------------------------------------------------------
#define APAD 40
#define A_ROWS 340
#define B_ROWS 576
#define A_BYTES (A_ROWS * APAD * 2)         // 27200
#define STAGE_BYTES (A_BYTES + B_ROWS * APAD * 2)  // 73280
#define CONV_SMEM (2 * STAGE_BYTES)

__device__ __forceinline__ void mma_16816(float* c, const uint32_t* a, const uint32_t* b) {
    asm volatile(
        "mma.sync.aligned.m16n8k16.row.col.f32.f16.f16.f32 "
        "{%0,%1,%2,%3}, {%4,%5,%6,%7}, {%8,%9}, {%0,%1,%2,%3};"
        : "+f"(c[0]), "+f"(c[1]), "+f"(c[2]), "+f"(c[3])
        : "r"(a[0]), "r"(a[1]), "r"(a[2]), "r"(a[3]), "r"(b[0]), "r"(b[1]));
}

__device__ __forceinline__ void ldsm_x4(uint32_t* r, uint32_t saddr) {
    asm volatile("ldmatrix.sync.aligned.m8n8.x4.shared.b16 {%0,%1,%2,%3}, [%4];"
                 : "=r"(r[0]), "=r"(r[1]), "=r"(r[2]), "=r"(r[3]) : "r"(saddr));
}

__device__ __forceinline__ void cp_async16(uint32_t dst, const void* src, int src_sz) {
    asm volatile("cp.async.cg.shared.global [%0], [%1], 16, %2;"
                 :: "r"(dst), "l"(src), "r"(src_sz) : "memory");
}
#define CP_COMMIT() asm volatile("cp.async.commit_group;" ::: "memory")
#define CP_WAIT0()  asm volatile("cp.async.wait_group 0;" ::: "memory")

template <int CIN, bool FINAL>
__global__ __launch_bounds__(256, 1)
void conv_mma(float* __restrict__ dout, const float* __restrict__ xres, int out_ch_off) {
    extern __shared__ __align__(16) char dyn[];
    __shared__ float s_bias[64];
    __shared__ float s_red[8][64];

    const int t = threadIdx.x;
    const int lane = t & 31;
    const int wid = t >> 5;
    const int gx0 = blockIdx.x * 32;
    const int gy0 = blockIdx.y * 8;
    const int b = blockIdx.z;
    const int NC = CIN / 32;

    const uint32_t su = (uint32_t)__cvta_generic_to_shared(dyn);
    const __half* inb = g_concat + (size_t)b * HW * CTOT;
    const __half* wkb = g_wk2h + (size_t)b * (9 * GC * CIN);

    if (t < 64) s_bias[t] = g_bk[b * GC + t];

    float acc[2][8][4];
    #pragma unroll
    for (int mt = 0; mt < 2; mt++)
        #pragma unroll
        for (int nt = 0; nt < 8; nt++)
            #pragma unroll
            for (int q = 0; q < 4; q++) acc[mt][nt][q] = 0.f;

    // issue cp.async for one chunk into a stage
    auto issue_chunk = [&](int c0, int stage) {
        uint32_t sbase = su + stage * STAGE_BYTES;
        // A: 340 halo rows x 4 chunks of 16B
        #pragma unroll
        for (int k = 0; k < 6; k++) {
            int i = t + k * 256;
            if (i < A_ROWS * 4) {
                int row = i >> 2, q = i & 3;
                int r = row / 34, cc = row - r * 34;
                int gy = gy0 + r - 1, gx = gx0 + cc - 1;
                bool ok = ((unsigned)gy < HH) && ((unsigned)gx < WW);
                const __half* src = ok ? (inb + (size_t)(gy * WW + gx) * CTOT + c0 + q * 8)
                                       : inb;
                cp_async16(sbase + (row * APAD + q * 8) * 2, src, ok ? 16 : 0);
            }
        }
        // B: 576 rows (tap*64+oc) x 4 chunks of 16B
        #pragma unroll
        for (int k = 0; k < 9; k++) {
            int i = t + k * 256;
            if (i < B_ROWS * 4) {
                int row = i >> 2, q = i & 3;
                const __half* src = wkb + (size_t)row * CIN + c0 + q * 8;
                cp_async16(sbase + A_BYTES + (row * APAD + q * 8) * 2, src, 16);
            }
        }
    };

    issue_chunk(0, 0);
    CP_COMMIT();

    // ldmatrix lane addressing
    const int a_m  = lane & 15;
    const int a_kh = lane >> 4;
    const int b_n  = (lane >> 4) * 8 + (lane & 7);
    const int b_kh = (lane >> 3) & 1;

    #pragma unroll 1
    for (int ic = 0; ic < NC; ic++) {
        const int s = ic & 1;
        const uint32_t sa_u = su + s * STAGE_BYTES;
        const uint32_t sb_u = sa_u + A_BYTES;

        CP_WAIT0();
        __syncthreads();
        if (ic + 1 < NC) {
            issue_chunk((ic + 1) * 32, s ^ 1);
            CP_COMMIT();
        }

        #pragma unroll 1
        for (int tap = 0; tap < 9; tap++) {
            const int dy = tap / 3 - 1, dx = tap % 3 - 1;
            const int arow = (wid + dy + 1) * 34 + dx + 1;
            const uint32_t btap = sb_u + (tap * 64) * (APAD * 2);
            #pragma unroll
            for (int k16 = 0; k16 < 2; k16++) {
                uint32_t af[2][4];
                #pragma unroll
                for (int mt = 0; mt < 2; mt++) {
                    uint32_t addr = sa_u + 2 * ((arow + mt * 16 + a_m) * APAD + k16 * 16 + a_kh * 8);
                    ldsm_x4(af[mt], addr);
                }
                uint32_t bf[8][2];
                #pragma unroll
                for (int j = 0; j < 4; j++) {
                    uint32_t r[4];
                    int n = j * 16 + b_n;
                    uint32_t addr = btap + 2 * (n * APAD + k16 * 16 + b_kh * 8);
                    ldsm_x4(r, addr);
                    bf[j * 2][0] = r[0]; bf[j * 2][1] = r[1];
                    bf[j * 2 + 1][0] = r[2]; bf[j * 2 + 1][1] = r[3];
                }
                #pragma unroll
                for (int mt = 0; mt < 2; mt++)
                    #pragma unroll
                    for (int nt = 0; nt < 8; nt++)
                        mma_16816(acc[mt][nt], af[mt], bf[nt]);
            }
        }
        __syncthreads();
    }

    // epilogue (+ fused GAP partials)
    const int gy = gy0 + wid;
    float sum0[8], sum1[8];
    #pragma unroll
    for (int nt = 0; nt < 8; nt++) { sum0[nt] = 0.f; sum1[nt] = 0.f; }

    #pragma unroll
    for (int mt = 0; mt < 2; mt++) {
        #pragma unroll
        for (int hi = 0; hi < 2; hi++) {
            int px = mt * 16 + (lane >> 2) + hi * 8;
            size_t pixidx = (size_t)gy * WW + gx0 + px;
            #pragma unroll
            for (int nt = 0; nt < 8; nt++) {
                int oc = nt * 8 + 2 * (lane & 3);
                float v0 = acc[mt][nt][hi * 2 + 0] + s_bias[oc];
                float v1 = acc[mt][nt][hi * 2 + 1] + s_bias[oc + 1];
                if (FINAL) {
                    dout[((size_t)b * GC + oc) * HW + pixidx] =
                        0.2f * v0 + xres[((size_t)b * GC + oc) * HW + pixidx];
                    dout[((size_t)b * GC + oc + 1) * HW + pixidx] =
                        0.2f * v1 + xres[((size_t)b * GC + oc + 1) * HW + pixidx];
                } else {
                    v0 = v0 >= 0.f ? v0 : 0.2f * v0;
                    v1 = v1 >= 0.f ? v1 : 0.2f * v1;
                    *(__half2*)&g_concat[((size_t)b * HW + pixidx) * CTOT + out_ch_off + oc] =
                        __floats2half2_rn(v0, v1);
                    sum0[nt] += v0;
                    sum1[nt] += v1;
                }
            }
        }
    }

    if (!FINAL) {
        #pragma unroll
        for (int nt = 0; nt < 8; nt++) {
            #pragma unroll
            for (int off = 16; off >= 4; off >>= 1) {
                sum0[nt] += __shfl_xor_sync(0xFFFFFFFFu, sum0[nt], off);
                sum1[nt] += __shfl_xor_sync(0xFFFFFFFFu, sum1[nt], off);
            }
        }
        if (lane < 4) {
            #pragma unroll
            for (int nt = 0; nt < 8; nt++) {
                int chl = nt * 8 + 2 * lane;
                s_red[wid][chl]     = sum0[nt];
                s_red[wid][chl + 1] = sum1[nt];
            }
        }
        __syncthreads();
        if (t < 64) {
            int tile = blockIdx.y * 3 + blockIdx.x;
            float s = 0.f;
            #pragma unroll
            for (int wv = 0; wv < 8; wv++) s += s_red[wv][t];
            g_partial[((size_t)b * 144 + tile) * 64 + t] = s;
        }
    }
}

// ---------------------------------------------------------------------------
// Host orchestration
// ---------------------------------------------------------------------------
extern "C" void kernel_launch(void* const* d_in, const int* in_sizes, int n_in,
                              void* d_out, int out_size) {
    const float* x = (const float*)d_in[0];
    const float *W[5], *Bv[5], *A1[5], *Ab1[5], *A2[5], *Ab2[5];
    for (int i = 0; i < 5; i++) {
        W[i]   = (const float*)d_in[1 + 6 * i + 0];
        Bv[i]  = (const float*)d_in[1 + 6 * i + 1];
        A1[i]  = (const float*)d_in[1 + 6 * i + 2];
        Ab1[i] = (const float*)d_in[1 + 6 * i + 3];
        A2[i]  = (const float*)d_in[1 + 6 * i + 4];
        Ab2[i] = (const float*)d_in[1 + 6 * i + 5];
    }
    float* out = (float*)d_out;

    cudaFuncSetAttribute(conv_mma<64,  false>, cudaFuncAttributeMaxDynamicSharedMemorySize, CONV_SMEM);
    cudaFuncSetAttribute(conv_mma<128, false>, cudaFuncAttributeMaxDynamicSharedMemorySize, CONV_SMEM);
    cudaFuncSetAttribute(conv_mma<192, false>, cudaFuncAttributeMaxDynamicSharedMemorySize, CONV_SMEM);
    cudaFuncSetAttribute(conv_mma<256, false>, cudaFuncAttributeMaxDynamicSharedMemorySize, CONV_SMEM);
    cudaFuncSetAttribute(conv_mma<320, true >, cudaFuncAttributeMaxDynamicSharedMemorySize, CONV_SMEM);

    dim3 cgrid(3, 12, NB);

    copyx_t<<<dim3(144, NB), 256>>>(x);

    // Layer 1 (cin=64)
    attn_kernel<64><<<NB, 128>>>(A1[0], Ab1[0], A2[0], Ab2[0], Bv[0], 144, 0);
    mix2h_kernel<64><<<(NB * 9 * GC * 32 + 255) / 256, 256>>>(W[0]);
    conv_mma<64, false><<<cgrid, 256, CONV_SMEM>>>(nullptr, nullptr, 64);

    // Layer 2 (cin=128)
    attn_kernel<128><<<NB, 128>>>(A1[1], Ab1[1], A2[1], Ab2[1], Bv[1], 36, 64);
    mix2h_kernel<128><<<(NB * 9 * GC * 64 + 255) / 256, 256>>>(W[1]);
    conv_mma<128, false><<<cgrid, 256, CONV_SMEM>>>(nullptr, nullptr, 128);

    // Layer 3 (cin=192)
    attn_kernel<192><<<NB, 128>>>(A1[2], Ab1[2], A2[2], Ab2[2], Bv[2], 36, 128);
    mix2h_kernel<192><<<(NB * 9 * GC * 96 + 255) / 256, 256>>>(W[2]);
    conv_mma<192, false><<<cgrid, 256, CONV_SMEM>>>(nullptr, nullptr, 192);

    // Layer 4 (cin=256)
    attn_kernel<256><<<NB, 128>>>(A1[3], Ab1[3], A2[3], Ab2[3], Bv[3], 36, 192);
    mix2h_kernel<256><<<(NB * 9 * GC * 128 + 255) / 256, 256>>>(W[3]);
    conv_mma<256, false><<<cgrid, 256, CONV_SMEM>>>(nullptr, nullptr, 256);

    // Layer 5 (cin=320) -> final output with fp32 residual from original x
    attn_kernel<320><<<NB, 128>>>(A1[4], Ab1[4], A2[4], Ab2[4], Bv[4], 36, 256);
    mix2h_kernel<320><<<(NB * 9 * GC * 160 + 255) / 256, 256>>>(W[4]);
    conv_mma<320, true><<<cgrid, 256, CONV_SMEM>>>(out, x, 0);
}

// round 10
// speedup vs baseline: 6.4473x; 1.0672x over previous
#include <cuda_runtime.h>
#include <cuda_fp16.h>
#include <cstdint>
#include <math.h>

#define NB   16
#define NF   64
#define GC   64
#define KK   8
#define HH   96
#define WW   96
#define HW   (HH*WW)
#define CTOT 320

// ---------------------------------------------------------------------------
// Scratch
// ---------------------------------------------------------------------------
__device__ __half g_concat[(size_t)NB * HW * CTOT];      // NHWC fp16
__device__ float  g_pooled[NB * CTOT];
__device__ float  g_attn[NB * KK];
__device__ float  g_bk[NB * GC];
__device__ __half g_wk2h[(size_t)NB * 9 * GC * CTOT];    // [b][tap][oc][c] fp16
__device__ float  g_partial[(size_t)NB * 144 * 64];      // GAP partials per tile

// ---------------------------------------------------------------------------
// NCHW fp32 -> NHWC fp16 transpose of input x, fused GAP partials (fp32).
// grid (144, 16), block 256.
// ---------------------------------------------------------------------------
__global__ void copyx_t(const float* __restrict__ x) {
    __shared__ float sm[64][65];
    __shared__ float red[4][64];
    int b = blockIdx.y;
    int p0 = blockIdx.x * 64;
    int t = threadIdx.x;
    #pragma unroll
    for (int i = 0; i < 16; i++) {
        int idx = t + i * 256;
        int c = idx >> 6, pl = idx & 63;
        sm[c][pl] = x[((size_t)b * 64 + c) * HW + p0 + pl];
    }
    __syncthreads();
    const int c = t & 63;
    float s = 0.f;
    #pragma unroll
    for (int i = 0; i < 16; i++) {
        int pl = (t >> 6) + 4 * i;
        float v = sm[c][pl];
        g_concat[((size_t)b * HW + p0 + pl) * CTOT + c] = __float2half(v);
        s += v;
    }
    red[t >> 6][c] = s;
    __syncthreads();
    if (t < 64)
        g_partial[((size_t)b * 144 + blockIdx.x) * 64 + t] =
            red[0][t] + red[1][t] + red[2][t] + red[3][t];
}

// ---------------------------------------------------------------------------
// Attention MLP per sample, with fused GAP-partial reduction for the newest
// 64 channels. grid(NB), block 128.
// ---------------------------------------------------------------------------
template <int CIN>
__global__ void attn_kernel(const float* __restrict__ aw1, const float* __restrict__ ab1,
                            const float* __restrict__ aw2, const float* __restrict__ ab2,
                            const float* __restrict__ bvec, int ntiles, int ch_off) {
    const int HID = CIN / 4;
    int b = blockIdx.x;
    int t = threadIdx.x;
    __shared__ float red[2][64];
    __shared__ float sp[CIN];
    __shared__ float sh[HID];
    __shared__ float sl[KK];
    __shared__ float sa[KK];

    {
        int ch = t & 63, grp = t >> 6;
        float s = 0.f;
        for (int tile = grp; tile < ntiles; tile += 2)
            s += g_partial[((size_t)b * 144 + tile) * 64 + ch];
        red[grp][ch] = s;
        __syncthreads();
        if (t < 64)
            g_pooled[b * CTOT + ch_off + t] = (red[0][t] + red[1][t]) * (1.f / (float)HW);
        __syncthreads();
    }

    for (int i = t; i < CIN; i += 128) sp[i] = g_pooled[b * CTOT + i];
    __syncthreads();
    if (t < HID) {
        float s = ab1[t];
        const float* row = aw1 + (size_t)t * CIN;
        for (int c = 0; c < CIN; c++) s += row[c] * sp[c];
        sh[t] = s > 0.f ? s : 0.f;
    }
    __syncthreads();
    if (t < KK) {
        float s = ab2[t];
        const float* row = aw2 + (size_t)t * HID;
        for (int j = 0; j < HID; j++) s += row[j] * sh[j];
        sl[t] = s;
    }
    __syncthreads();
    if (t == 0) {
        float m = sl[0];
        for (int k = 1; k < KK; k++) m = fmaxf(m, sl[k]);
        float den = 0.f;
        for (int k = 0; k < KK; k++) { float e = expf(sl[k] - m); sa[k] = e; den += e; }
        float inv = 1.f / den;
        for (int k = 0; k < KK; k++) { sa[k] *= inv; g_attn[b * KK + k] = sa[k]; }
    }
    __syncthreads();
    if (t < GC) {
        float s = 0.f;
        #pragma unroll
        for (int k = 0; k < KK; k++) s += sa[k] * bvec[k * GC + t];
        g_bk[b * GC + t] = s;
    }
}

// ---------------------------------------------------------------------------
// Mix expert weights -> fp16 tap-major layout g_wk2h[b][tap][oc][c].
// ---------------------------------------------------------------------------
template <int CIN>
__global__ void mix2h_kernel(const float* __restrict__ w) {
    const int per_b = 9 * GC * (CIN / 2);
    int i = blockIdx.x * 256 + threadIdx.x;
    if (i >= NB * per_b) return;
    int b = i / per_b;
    int r = i - b * per_b;
    int cc  = (r % (CIN / 2)) * 2;
    int tap = (r / (CIN / 2)) % 9;
    int oc  = r / (9 * (CIN / 2));
    float s0 = 0.f, s1 = 0.f;
    #pragma unroll
    for (int k = 0; k < KK; k++) {
        float a = g_attn[b * KK + k];
        size_t base = (((size_t)k * GC + oc) * CIN + cc) * 9 + tap;
        s0 += a * w[base];
        s1 += a * w[base + 9];
    }
    *(__half2*)&g_wk2h[(((size_t)b * 9 + tap) * GC + oc) * CIN + cc] =
        __floats2half2_rn(s0, s1);
}

// ---------------------------------------------------------------------------
// fp16 mma.sync conv, cp.async whole-chunk double-buffered pipeline.
// CTA: 512 pixels (16 rows x 32 cols) x 64 oc. 16 warps, each 32px x 64oc.
// Stage smem = A halo (612 rows x 40 halves) + B all 9 taps (576 rows x 40).
// grid (3, 6, NB), block 512, dynamic smem 2*95040 = 190080.
// ---------------------------------------------------------------------------
#define APAD 40
#define A_ROWS 612
#define B_ROWS 576
#define A_BYTES (A_ROWS * APAD * 2)                 // 48960
#define STAGE_BYTES (A_BYTES + B_ROWS * APAD * 2)   // 95040
#define CONV_SMEM (2 * STAGE_BYTES)                 // 190080

__device__ __forceinline__ void mma_16816(float* c, const uint32_t* a, const uint32_t* b) {
    asm volatile(
        "mma.sync.aligned.m16n8k16.row.col.f32.f16.f16.f32 "
        "{%0,%1,%2,%3}, {%4,%5,%6,%7}, {%8,%9}, {%0,%1,%2,%3};"
        : "+f"(c[0]), "+f"(c[1]), "+f"(c[2]), "+f"(c[3])
        : "r"(a[0]), "r"(a[1]), "r"(a[2]), "r"(a[3]), "r"(b[0]), "r"(b[1]));
}

__device__ __forceinline__ void ldsm_x4(uint32_t* r, uint32_t saddr) {
    asm volatile("ldmatrix.sync.aligned.m8n8.x4.shared.b16 {%0,%1,%2,%3}, [%4];"
                 : "=r"(r[0]), "=r"(r[1]), "=r"(r[2]), "=r"(r[3]) : "r"(saddr));
}

__device__ __forceinline__ void cp_async16(uint32_t dst, const void* src, int src_sz) {
    asm volatile("cp.async.cg.shared.global [%0], [%1], 16, %2;"
                 :: "r"(dst), "l"(src), "r"(src_sz) : "memory");
}
#define CP_COMMIT() asm volatile("cp.async.commit_group;" ::: "memory")
#define CP_WAIT0()  asm volatile("cp.async.wait_group 0;" ::: "memory")

template <int CIN, bool FINAL>
__global__ __launch_bounds__(512, 1)
void conv_mma(float* __restrict__ dout, const float* __restrict__ xres, int out_ch_off) {
    extern __shared__ __align__(16) char dyn[];
    __shared__ float s_bias[64];
    __shared__ float s_red[16][64];

    const int t = threadIdx.x;
    const int lane = t & 31;
    const int wid = t >> 5;                 // 0..15 -> image row within tile
    const int gx0 = blockIdx.x * 32;
    const int gy0 = blockIdx.y * 16;
    const int b = blockIdx.z;
    const int NC = CIN / 32;

    const uint32_t su = (uint32_t)__cvta_generic_to_shared(dyn);
    const __half* inb = g_concat + (size_t)b * HW * CTOT;
    const __half* wkb = g_wk2h + (size_t)b * (9 * GC * CIN);

    if (t < 64) s_bias[t] = g_bk[b * GC + t];

    float acc[2][8][4];
    #pragma unroll
    for (int mt = 0; mt < 2; mt++)
        #pragma unroll
        for (int nt = 0; nt < 8; nt++)
            #pragma unroll
            for (int q = 0; q < 4; q++) acc[mt][nt][q] = 0.f;

    auto issue_chunk = [&](int c0, int stage) {
        uint32_t sbase = su + stage * STAGE_BYTES;
        // A: 612 halo rows x 4 chunks of 16B = 2448 segments
        #pragma unroll
        for (int k = 0; k < 5; k++) {
            int i = t + k * 512;
            if (i < A_ROWS * 4) {
                int row = i >> 2, q = i & 3;
                int r = row / 34, cc = row - r * 34;
                int gy = gy0 + r - 1, gx = gx0 + cc - 1;
                bool ok = ((unsigned)gy < HH) && ((unsigned)gx < WW);
                const __half* src = ok ? (inb + (size_t)(gy * WW + gx) * CTOT + c0 + q * 8)
                                       : inb;
                cp_async16(sbase + (row * APAD + q * 8) * 2, src, ok ? 16 : 0);
            }
        }
        // B: 576 rows (tap*64+oc) x 4 chunks of 16B = 2304 segments
        #pragma unroll
        for (int k = 0; k < 5; k++) {
            int i = t + k * 512;
            if (i < B_ROWS * 4) {
                int row = i >> 2, q = i & 3;
                const __half* src = wkb + (size_t)row * CIN + c0 + q * 8;
                cp_async16(sbase + A_BYTES + (row * APAD + q * 8) * 2, src, 16);
            }
        }
    };

    issue_chunk(0, 0);
    CP_COMMIT();

    const int a_m  = lane & 15;
    const int a_kh = lane >> 4;
    const int b_n  = (lane >> 4) * 8 + (lane & 7);
    const int b_kh = (lane >> 3) & 1;

    #pragma unroll 1
    for (int ic = 0; ic < NC; ic++) {
        const int s = ic & 1;
        const uint32_t sa_u = su + s * STAGE_BYTES;
        const uint32_t sb_u = sa_u + A_BYTES;

        CP_WAIT0();
        __syncthreads();
        if (ic + 1 < NC) {
            issue_chunk((ic + 1) * 32, s ^ 1);
            CP_COMMIT();
        }

        #pragma unroll 1
        for (int tap = 0; tap < 9; tap++) {
            const int dy = tap / 3 - 1, dx = tap % 3 - 1;
            const int arow = (wid + dy + 1) * 34 + dx + 1;
            const uint32_t btap = sb_u + (tap * 64) * (APAD * 2);
            #pragma unroll
            for (int k16 = 0; k16 < 2; k16++) {
                uint32_t af[2][4];
                #pragma unroll
                for (int mt = 0; mt < 2; mt++) {
                    uint32_t addr = sa_u + 2 * ((arow + mt * 16 + a_m) * APAD + k16 * 16 + a_kh * 8);
                    ldsm_x4(af[mt], addr);
                }
                uint32_t bf[8][2];
                #pragma unroll
                for (int j = 0; j < 4; j++) {
                    uint32_t r[4];
                    int n = j * 16 + b_n;
                    uint32_t addr = btap + 2 * (n * APAD + k16 * 16 + b_kh * 8);
                    ldsm_x4(r, addr);
                    bf[j * 2][0] = r[0]; bf[j * 2][1] = r[1];
                    bf[j * 2 + 1][0] = r[2]; bf[j * 2 + 1][1] = r[3];
                }
                #pragma unroll
                for (int mt = 0; mt < 2; mt++)
                    #pragma unroll
                    for (int nt = 0; nt < 8; nt++)
                        mma_16816(acc[mt][nt], af[mt], bf[nt]);
            }
        }
        __syncthreads();
    }

    // epilogue (+ fused GAP partials)
    const int gy = gy0 + wid;
    float sum0[8], sum1[8];
    #pragma unroll
    for (int nt = 0; nt < 8; nt++) { sum0[nt] = 0.f; sum1[nt] = 0.f; }

    #pragma unroll
    for (int mt = 0; mt < 2; mt++) {
        #pragma unroll
        for (int hi = 0; hi < 2; hi++) {
            int px = mt * 16 + (lane >> 2) + hi * 8;
            size_t pixidx = (size_t)gy * WW + gx0 + px;
            #pragma unroll
            for (int nt = 0; nt < 8; nt++) {
                int oc = nt * 8 + 2 * (lane & 3);
                float v0 = acc[mt][nt][hi * 2 + 0] + s_bias[oc];
                float v1 = acc[mt][nt][hi * 2 + 1] + s_bias[oc + 1];
                if (FINAL) {
                    dout[((size_t)b * GC + oc) * HW + pixidx] =
                        0.2f * v0 + xres[((size_t)b * GC + oc) * HW + pixidx];
                    dout[((size_t)b * GC + oc + 1) * HW + pixidx] =
                        0.2f * v1 + xres[((size_t)b * GC + oc + 1) * HW + pixidx];
                } else {
                    v0 = v0 >= 0.f ? v0 : 0.2f * v0;
                    v1 = v1 >= 0.f ? v1 : 0.2f * v1;
                    *(__half2*)&g_concat[((size_t)b * HW + pixidx) * CTOT + out_ch_off + oc] =
                        __floats2half2_rn(v0, v1);
                    sum0[nt] += v0;
                    sum1[nt] += v1;
                }
            }
        }
    }

    if (!FINAL) {
        #pragma unroll
        for (int nt = 0; nt < 8; nt++) {
            #pragma unroll
            for (int off = 16; off >= 4; off >>= 1) {
                sum0[nt] += __shfl_xor_sync(0xFFFFFFFFu, sum0[nt], off);
                sum1[nt] += __shfl_xor_sync(0xFFFFFFFFu, sum1[nt], off);
            }
        }
        if (lane < 4) {
            #pragma unroll
            for (int nt = 0; nt < 8; nt++) {
                int chl = nt * 8 + 2 * lane;
                s_red[wid][chl]     = sum0[nt];
                s_red[wid][chl + 1] = sum1[nt];
            }
        }
        __syncthreads();
        if (t < 64) {
            int tile = blockIdx.y * 3 + blockIdx.x;
            float s = 0.f;
            #pragma unroll
            for (int wv = 0; wv < 16; wv++) s += s_red[wv][t];
            g_partial[((size_t)b * 144 + tile) * 64 + t] = s;
        }
    }
}

// ---------------------------------------------------------------------------
// Host orchestration
// ---------------------------------------------------------------------------
extern "C" void kernel_launch(void* const* d_in, const int* in_sizes, int n_in,
                              void* d_out, int out_size) {
    const float* x = (const float*)d_in[0];
    const float *W[5], *Bv[5], *A1[5], *Ab1[5], *A2[5], *Ab2[5];
    for (int i = 0; i < 5; i++) {
        W[i]   = (const float*)d_in[1 + 6 * i + 0];
        Bv[i]  = (const float*)d_in[1 + 6 * i + 1];
        A1[i]  = (const float*)d_in[1 + 6 * i + 2];
        Ab1[i] = (const float*)d_in[1 + 6 * i + 3];
        A2[i]  = (const float*)d_in[1 + 6 * i + 4];
        Ab2[i] = (const float*)d_in[1 + 6 * i + 5];
    }
    float* out = (float*)d_out;

    cudaFuncSetAttribute(conv_mma<64,  false>, cudaFuncAttributeMaxDynamicSharedMemorySize, CONV_SMEM);
    cudaFuncSetAttribute(conv_mma<128, false>, cudaFuncAttributeMaxDynamicSharedMemorySize, CONV_SMEM);
    cudaFuncSetAttribute(conv_mma<192, false>, cudaFuncAttributeMaxDynamicSharedMemorySize, CONV_SMEM);
    cudaFuncSetAttribute(conv_mma<256, false>, cudaFuncAttributeMaxDynamicSharedMemorySize, CONV_SMEM);
    cudaFuncSetAttribute(conv_mma<320, true >, cudaFuncAttributeMaxDynamicSharedMemorySize, CONV_SMEM);

    dim3 cgrid(3, 6, NB);

    copyx_t<<<dim3(144, NB), 256>>>(x);

    // Layer 1 (cin=64)
    attn_kernel<64><<<NB, 128>>>(A1[0], Ab1[0], A2[0], Ab2[0], Bv[0], 144, 0);
    mix2h_kernel<64><<<(NB * 9 * GC * 32 + 255) / 256, 256>>>(W[0]);
    conv_mma<64, false><<<cgrid, 512, CONV_SMEM>>>(nullptr, nullptr, 64);

    // Layer 2 (cin=128)
    attn_kernel<128><<<NB, 128>>>(A1[1], Ab1[1], A2[1], Ab2[1], Bv[1], 18, 64);
    mix2h_kernel<128><<<(NB * 9 * GC * 64 + 255) / 256, 256>>>(W[1]);
    conv_mma<128, false><<<cgrid, 512, CONV_SMEM>>>(nullptr, nullptr, 128);

    // Layer 3 (cin=192)
    attn_kernel<192><<<NB, 128>>>(A1[2], Ab1[2], A2[2], Ab2[2], Bv[2], 18, 128);
    mix2h_kernel<192><<<(NB * 9 * GC * 96 + 255) / 256, 256>>>(W[2]);
    conv_mma<192, false><<<cgrid, 512, CONV_SMEM>>>(nullptr, nullptr, 192);

    // Layer 4 (cin=256)
    attn_kernel<256><<<NB, 128>>>(A1[3], Ab1[3], A2[3], Ab2[3], Bv[3], 18, 192);
    mix2h_kernel<256><<<(NB * 9 * GC * 128 + 255) / 256, 256>>>(W[3]);
    conv_mma<256, false><<<cgrid, 512, CONV_SMEM>>>(nullptr, nullptr, 256);

    // Layer 5 (cin=320) -> final output with fp32 residual from original x
    attn_kernel<320><<<NB, 128>>>(A1[4], Ab1[4], A2[4], Ab2[4], Bv[4], 18, 256);
    mix2h_kernel<320><<<(NB * 9 * GC * 160 + 255) / 256, 256>>>(W[4]);
    conv_mma<320, true><<<cgrid, 512, CONV_SMEM>>>(out, x, 0);
}

// round 11
// speedup vs baseline: 7.3895x; 1.1461x over previous
#include <cuda_runtime.h>
#include <cuda_fp16.h>
#include <cstdint>
#include <math.h>

#define NB   16
#define NF   64
#define GC   64
#define KK   8
#define HH   96
#define WW   96
#define HW   (HH*WW)
#define CTOT 320

// ---------------------------------------------------------------------------
// Scratch
// ---------------------------------------------------------------------------
__device__ __half g_concat[(size_t)NB * HW * CTOT];      // NHWC fp16
__device__ float  g_pooled[NB * CTOT];
__device__ float  g_attn[NB * KK];
__device__ float  g_bk[NB * GC];
__device__ __half g_wk2h[(size_t)NB * 9 * GC * CTOT];    // [b][tap][oc][c] fp16
__device__ float  g_partial[(size_t)NB * 144 * 64];      // GAP partials per tile

// ---------------------------------------------------------------------------
// NCHW fp32 -> NHWC fp16 transpose of input x, fused GAP partials (fp32).
// grid (144, 16), block 256.
// ---------------------------------------------------------------------------
__global__ void copyx_t(const float* __restrict__ x) {
    __shared__ float sm[64][65];
    __shared__ float red[4][64];
    int b = blockIdx.y;
    int p0 = blockIdx.x * 64;
    int t = threadIdx.x;
    #pragma unroll
    for (int i = 0; i < 16; i++) {
        int idx = t + i * 256;
        int c = idx >> 6, pl = idx & 63;
        sm[c][pl] = x[((size_t)b * 64 + c) * HW + p0 + pl];
    }
    __syncthreads();
    const int c = t & 63;
    float s = 0.f;
    #pragma unroll
    for (int i = 0; i < 16; i++) {
        int pl = (t >> 6) + 4 * i;
        float v = sm[c][pl];
        g_concat[((size_t)b * HW + p0 + pl) * CTOT + c] = __float2half(v);
        s += v;
    }
    red[t >> 6][c] = s;
    __syncthreads();
    if (t < 64)
        g_partial[((size_t)b * 144 + blockIdx.x) * 64 + t] =
            red[0][t] + red[1][t] + red[2][t] + red[3][t];
}

// ---------------------------------------------------------------------------
// Attention MLP per sample, with fused GAP-partial reduction for the newest
// 64 channels. grid(NB), block 128.
// ---------------------------------------------------------------------------
template <int CIN>
__global__ void attn_kernel(const float* __restrict__ aw1, const float* __restrict__ ab1,
                            const float* __restrict__ aw2, const float* __restrict__ ab2,
                            const float* __restrict__ bvec, int ntiles, int ch_off) {
    const int HID = CIN / 4;
    int b = blockIdx.x;
    int t = threadIdx.x;
    __shared__ float red[2][64];
    __shared__ float sp[CIN];
    __shared__ float sh[HID];
    __shared__ float sl[KK];
    __shared__ float sa[KK];

    {
        int ch = t & 63, grp = t >> 6;
        float s = 0.f;
        for (int tile = grp; tile < ntiles; tile += 2)
            s += g_partial[((size_t)b * 144 + tile) * 64 + ch];
        red[grp][ch] = s;
        __syncthreads();
        if (t < 64)
            g_pooled[b * CTOT + ch_off + t] = (red[0][t] + red[1][t]) * (1.f / (float)HW);
        __syncthreads();
    }

    for (int i = t; i < CIN; i += 128) sp[i] = g_pooled[b * CTOT + i];
    __syncthreads();
    if (t < HID) {
        float s = ab1[t];
        const float* row = aw1 + (size_t)t * CIN;
        for (int c = 0; c < CIN; c++) s += row[c] * sp[c];
        sh[t] = s > 0.f ? s : 0.f;
    }
    __syncthreads();
    if (t < KK) {
        float s = ab2[t];
        const float* row = aw2 + (size_t)t * HID;
        for (int j = 0; j < HID; j++) s += row[j] * sh[j];
        sl[t] = s;
    }
    __syncthreads();
    if (t == 0) {
        float m = sl[0];
        for (int k = 1; k < KK; k++) m = fmaxf(m, sl[k]);
        float den = 0.f;
        for (int k = 0; k < KK; k++) { float e = expf(sl[k] - m); sa[k] = e; den += e; }
        float inv = 1.f / den;
        for (int k = 0; k < KK; k++) { sa[k] *= inv; g_attn[b * KK + k] = sa[k]; }
    }
    __syncthreads();
    if (t < GC) {
        float s = 0.f;
        #pragma unroll
        for (int k = 0; k < KK; k++) s += sa[k] * bvec[k * GC + t];
        g_bk[b * GC + t] = s;
    }
}

// ---------------------------------------------------------------------------
// Batched weight mixing: each thread owns (oc, c-pair), loads all 8 experts'
// 18 consecutive floats (9 taps x 2 channels) ONCE, applies all 16 samples'
// attention vectors. W gmem traffic drops 16x vs per-sample mixing.
// grid: (64 * CIN/2) / 128, block 128.
// ---------------------------------------------------------------------------
template <int CIN>
__global__ __launch_bounds__(128)
void mix2h_batched(const float* __restrict__ w) {
    __shared__ float s_attn[NB][KK];
    int t = threadIdx.x;
    if (t < NB * KK) s_attn[t / KK][t % KK] = g_attn[t];
    __syncthreads();

    int idx = blockIdx.x * 128 + t;
    const int NPC = CIN / 2;
    if (idx >= GC * NPC) return;
    int oc = idx / NPC;
    int cp = idx - oc * NPC;
    int cc = cp * 2;

    // load 8 experts x 18 consecutive floats
    float wreg[KK][18];
    #pragma unroll
    for (int k = 0; k < KK; k++) {
        const float* src = w + (((size_t)k * GC + oc) * CIN + cc) * 9;
        #pragma unroll
        for (int j = 0; j < 18; j++) wreg[k][j] = src[j];
    }

    #pragma unroll 1
    for (int b = 0; b < NB; b++) {
        float a[KK];
        #pragma unroll
        for (int k = 0; k < KK; k++) a[k] = s_attn[b][k];
        float s[18];
        #pragma unroll
        for (int j = 0; j < 18; j++) {
            float v = 0.f;
            #pragma unroll
            for (int k = 0; k < KK; k++) v += a[k] * wreg[k][j];
            s[j] = v;
        }
        __half* dst = g_wk2h + (size_t)b * (9 * GC * CIN);
        #pragma unroll
        for (int tap = 0; tap < 9; tap++) {
            *(__half2*)&dst[(((size_t)tap * GC + oc) * CIN) + cc] =
                __floats2half2_rn(s[tap], s[tap + 9]);
        }
    }
}

// ---------------------------------------------------------------------------
// fp16 mma.sync conv, cp.async whole-chunk double-buffered pipeline.
// CTA: 512 pixels (16 rows x 32 cols) x 64 oc. 16 warps, each 32px x 64oc.
// Stage smem = A halo (612 rows x 40 halves) + B all 9 taps (576 rows x 40).
// grid (3, 6, NB), block 512, dynamic smem 2*95040 = 190080.
// One __syncthreads per chunk (top barrier orders readers vs next writer).
// ---------------------------------------------------------------------------
#define APAD 40
#define A_ROWS 612
#define B_ROWS 576
#define A_BYTES (A_ROWS * APAD * 2)                 // 48960
#define STAGE_BYTES (A_BYTES + B_ROWS * APAD * 2)   // 95040
#define CONV_SMEM (2 * STAGE_BYTES)                 // 190080

__device__ __forceinline__ void mma_16816(float* c, const uint32_t* a, const uint32_t* b) {
    asm volatile(
        "mma.sync.aligned.m16n8k16.row.col.f32.f16.f16.f32 "
        "{%0,%1,%2,%3}, {%4,%5,%6,%7}, {%8,%9}, {%0,%1,%2,%3};"
        : "+f"(c[0]), "+f"(c[1]), "+f"(c[2]), "+f"(c[3])
        : "r"(a[0]), "r"(a[1]), "r"(a[2]), "r"(a[3]), "r"(b[0]), "r"(b[1]));
}

__device__ __forceinline__ void ldsm_x4(uint32_t* r, uint32_t saddr) {
    asm volatile("ldmatrix.sync.aligned.m8n8.x4.shared.b16 {%0,%1,%2,%3}, [%4];"
                 : "=r"(r[0]), "=r"(r[1]), "=r"(r[2]), "=r"(r[3]) : "r"(saddr));
}

__device__ __forceinline__ void cp_async16(uint32_t dst, const void* src, int src_sz) {
    asm volatile("cp.async.cg.shared.global [%0], [%1], 16, %2;"
                 :: "r"(dst), "l"(src), "r"(src_sz) : "memory");
}
#define CP_COMMIT() asm volatile("cp.async.commit_group;" ::: "memory")
#define CP_WAIT0()  asm volatile("cp.async.wait_group 0;" ::: "memory")

template <int CIN, bool FINAL>
__global__ __launch_bounds__(512, 1)
void conv_mma(float* __restrict__ dout, const float* __restrict__ xres, int out_ch_off) {
    extern __shared__ __align__(16) char dyn[];
    __shared__ float s_bias[64];
    __shared__ float s_red[16][64];

    const int t = threadIdx.x;
    const int lane = t & 31;
    const int wid = t >> 5;                 // 0..15 -> image row within tile
    const int gx0 = blockIdx.x * 32;
    const int gy0 = blockIdx.y * 16;
    const int b = blockIdx.z;
    const int NC = CIN / 32;

    const uint32_t su = (uint32_t)__cvta_generic_to_shared(dyn);
    const __half* inb = g_concat + (size_t)b * HW * CTOT;
    const __half* wkb = g_wk2h + (size_t)b * (9 * GC * CIN);

    if (t < 64) s_bias[t] = g_bk[b * GC + t];

    float acc[2][8][4];
    #pragma unroll
    for (int mt = 0; mt < 2; mt++)
        #pragma unroll
        for (int nt = 0; nt < 8; nt++)
            #pragma unroll
            for (int q = 0; q < 4; q++) acc[mt][nt][q] = 0.f;

    auto issue_chunk = [&](int c0, int stage) {
        uint32_t sbase = su + stage * STAGE_BYTES;
        #pragma unroll
        for (int k = 0; k < 5; k++) {
            int i = t + k * 512;
            if (i < A_ROWS * 4) {
                int row = i >> 2, q = i & 3;
                int r = row / 34, cc = row - r * 34;
                int gy = gy0 + r - 1, gx = gx0 + cc - 1;
                bool ok = ((unsigned)gy < HH) && ((unsigned)gx < WW);
                const __half* src = ok ? (inb + (size_t)(gy * WW + gx) * CTOT + c0 + q * 8)
                                       : inb;
                cp_async16(sbase + (row * APAD + q * 8) * 2, src, ok ? 16 : 0);
            }
        }
        #pragma unroll
        for (int k = 0; k < 5; k++) {
            int i = t + k * 512;
            if (i < B_ROWS * 4) {
                int row = i >> 2, q = i & 3;
                const __half* src = wkb + (size_t)row * CIN + c0 + q * 8;
                cp_async16(sbase + A_BYTES + (row * APAD + q * 8) * 2, src, 16);
            }
        }
    };

    issue_chunk(0, 0);
    CP_COMMIT();

    const int a_m  = lane & 15;
    const int a_kh = lane >> 4;
    const int b_n  = (lane >> 4) * 8 + (lane & 7);
    const int b_kh = (lane >> 3) & 1;

    #pragma unroll 1
    for (int ic = 0; ic < NC; ic++) {
        const int s = ic & 1;
        const uint32_t sa_u = su + s * STAGE_BYTES;
        const uint32_t sb_u = sa_u + A_BYTES;

        CP_WAIT0();
        __syncthreads();     // stage s full; also orders prior readers of s^1
        if (ic + 1 < NC) {
            issue_chunk((ic + 1) * 32, s ^ 1);
            CP_COMMIT();
        }

        #pragma unroll 1
        for (int tap = 0; tap < 9; tap++) {
            const int dy = tap / 3 - 1, dx = tap % 3 - 1;
            const int arow = (wid + dy + 1) * 34 + dx + 1;
            const uint32_t btap = sb_u + (tap * 64) * (APAD * 2);
            #pragma unroll
            for (int k16 = 0; k16 < 2; k16++) {
                uint32_t af[2][4];
                #pragma unroll
                for (int mt = 0; mt < 2; mt++) {
                    uint32_t addr = sa_u + 2 * ((arow + mt * 16 + a_m) * APAD + k16 * 16 + a_kh * 8);
                    ldsm_x4(af[mt], addr);
                }
                uint32_t bf[8][2];
                #pragma unroll
                for (int j = 0; j < 4; j++) {
                    uint32_t r[4];
                    int n = j * 16 + b_n;
                    uint32_t addr = btap + 2 * (n * APAD + k16 * 16 + b_kh * 8);
                    ldsm_x4(r, addr);
                    bf[j * 2][0] = r[0]; bf[j * 2][1] = r[1];
                    bf[j * 2 + 1][0] = r[2]; bf[j * 2 + 1][1] = r[3];
                }
                #pragma unroll
                for (int mt = 0; mt < 2; mt++)
                    #pragma unroll
                    for (int nt = 0; nt < 8; nt++)
                        mma_16816(acc[mt][nt], af[mt], bf[nt]);
            }
        }
        // no end-of-chunk barrier: next iteration's top barrier provides the
        // ordering before stage s is overwritten (writer issues after it).
    }

    // epilogue (+ fused GAP partials)
    const int gy = gy0 + wid;
    float sum0[8], sum1[8];
    #pragma unroll
    for (int nt = 0; nt < 8; nt++) { sum0[nt] = 0.f; sum1[nt] = 0.f; }

    #pragma unroll
    for (int mt = 0; mt < 2; mt++) {
        #pragma unroll
        for (int hi = 0; hi < 2; hi++) {
            int px = mt * 16 + (lane >> 2) + hi * 8;
            size_t pixidx = (size_t)gy * WW + gx0 + px;
            #pragma unroll
            for (int nt = 0; nt < 8; nt++) {
                int oc = nt * 8 + 2 * (lane & 3);
                float v0 = acc[mt][nt][hi * 2 + 0] + s_bias[oc];
                float v1 = acc[mt][nt][hi * 2 + 1] + s_bias[oc + 1];
                if (FINAL) {
                    dout[((size_t)b * GC + oc) * HW + pixidx] =
                        0.2f * v0 + xres[((size_t)b * GC + oc) * HW + pixidx];
                    dout[((size_t)b * GC + oc + 1) * HW + pixidx] =
                        0.2f * v1 + xres[((size_t)b * GC + oc + 1) * HW + pixidx];
                } else {
                    v0 = v0 >= 0.f ? v0 : 0.2f * v0;
                    v1 = v1 >= 0.f ? v1 : 0.2f * v1;
                    *(__half2*)&g_concat[((size_t)b * HW + pixidx) * CTOT + out_ch_off + oc] =
                        __floats2half2_rn(v0, v1);
                    sum0[nt] += v0;
                    sum1[nt] += v1;
                }
            }
        }
    }

    if (!FINAL) {
        #pragma unroll
        for (int nt = 0; nt < 8; nt++) {
            #pragma unroll
            for (int off = 16; off >= 4; off >>= 1) {
                sum0[nt] += __shfl_xor_sync(0xFFFFFFFFu, sum0[nt], off);
                sum1[nt] += __shfl_xor_sync(0xFFFFFFFFu, sum1[nt], off);
            }
        }
        if (lane < 4) {
            #pragma unroll
            for (int nt = 0; nt < 8; nt++) {
                int chl = nt * 8 + 2 * lane;
                s_red[wid][chl]     = sum0[nt];
                s_red[wid][chl + 1] = sum1[nt];
            }
        }
        __syncthreads();
        if (t < 64) {
            int tile = blockIdx.y * 3 + blockIdx.x;
            float s = 0.f;
            #pragma unroll
            for (int wv = 0; wv < 16; wv++) s += s_red[wv][t];
            g_partial[((size_t)b * 144 + tile) * 64 + t] = s;
        }
    }
}

// ---------------------------------------------------------------------------
// Host orchestration
// ---------------------------------------------------------------------------
extern "C" void kernel_launch(void* const* d_in, const int* in_sizes, int n_in,
                              void* d_out, int out_size) {
    const float* x = (const float*)d_in[0];
    const float *W[5], *Bv[5], *A1[5], *Ab1[5], *A2[5], *Ab2[5];
    for (int i = 0; i < 5; i++) {
        W[i]   = (const float*)d_in[1 + 6 * i + 0];
        Bv[i]  = (const float*)d_in[1 + 6 * i + 1];
        A1[i]  = (const float*)d_in[1 + 6 * i + 2];
        Ab1[i] = (const float*)d_in[1 + 6 * i + 3];
        A2[i]  = (const float*)d_in[1 + 6 * i + 4];
        Ab2[i] = (const float*)d_in[1 + 6 * i + 5];
    }
    float* out = (float*)d_out;

    cudaFuncSetAttribute(conv_mma<64,  false>, cudaFuncAttributeMaxDynamicSharedMemorySize, CONV_SMEM);
    cudaFuncSetAttribute(conv_mma<128, false>, cudaFuncAttributeMaxDynamicSharedMemorySize, CONV_SMEM);
    cudaFuncSetAttribute(conv_mma<192, false>, cudaFuncAttributeMaxDynamicSharedMemorySize, CONV_SMEM);
    cudaFuncSetAttribute(conv_mma<256, false>, cudaFuncAttributeMaxDynamicSharedMemorySize, CONV_SMEM);
    cudaFuncSetAttribute(conv_mma<320, true >, cudaFuncAttributeMaxDynamicSharedMemorySize, CONV_SMEM);

    dim3 cgrid(3, 6, NB);

    copyx_t<<<dim3(144, NB), 256>>>(x);

    // Layer 1 (cin=64)
    attn_kernel<64><<<NB, 128>>>(A1[0], Ab1[0], A2[0], Ab2[0], Bv[0], 144, 0);
    mix2h_batched<64><<<(GC * 32 + 127) / 128, 128>>>(W[0]);
    conv_mma<64, false><<<cgrid, 512, CONV_SMEM>>>(nullptr, nullptr, 64);

    // Layer 2 (cin=128)
    attn_kernel<128><<<NB, 128>>>(A1[1], Ab1[1], A2[1], Ab2[1], Bv[1], 18, 64);
    mix2h_batched<128><<<(GC * 64 + 127) / 128, 128>>>(W[1]);
    conv_mma<128, false><<<cgrid, 512, CONV_SMEM>>>(nullptr, nullptr, 128);

    // Layer 3 (cin=192)
    attn_kernel<192><<<NB, 128>>>(A1[2], Ab1[2], A2[2], Ab2[2], Bv[2], 18, 128);
    mix2h_batched<192><<<(GC * 96 + 127) / 128, 128>>>(W[2]);
    conv_mma<192, false><<<cgrid, 512, CONV_SMEM>>>(nullptr, nullptr, 192);

    // Layer 4 (cin=256)
    attn_kernel<256><<<NB, 128>>>(A1[3], Ab1[3], A2[3], Ab2[3], Bv[3], 18, 192);
    mix2h_batched<256><<<(GC * 128 + 127) / 128, 128>>>(W[3]);
    conv_mma<256, false><<<cgrid, 512, CONV_SMEM>>>(nullptr, nullptr, 256);

    // Layer 5 (cin=320) -> final output with fp32 residual from original x
    attn_kernel<320><<<NB, 128>>>(A1[4], Ab1[4], A2[4], Ab2[4], Bv[4], 18, 256);
    mix2h_batched<320><<<(GC * 160 + 127) / 128, 128>>>(W[4]);
    conv_mma<320, true><<<cgrid, 512, CONV_SMEM>>>(out, x, 0);
}